// round 5
// baseline (speedup 1.0000x reference)
#include <cuda_runtime.h>
#include <cstdint>

#define B_ 16
#define O_ 64
#define I_ 512
#define D_ 256
#define OPB 8    // o-values per finish block
#define SOB 4    // o-values per score block

// ---------------- scratch (no allocation allowed) ----------------
__device__ float g_qp[B_ * O_ * D_];    // [b][o][h]  qp' = q@W1q^T + b1
__device__ float g_kpt[B_ * D_ * I_];   // [b][h][i]  kp^T
__device__ float g_sc[B_ * O_ * I_];    // [b][o][i]  raw scores

// ---------------- f32x2 packed helpers ----------------
__device__ __forceinline__ unsigned long long pack2(float lo, float hi) {
    unsigned long long r;
    asm("mov.b64 %0, {%1, %2};" : "=l"(r) : "f"(lo), "f"(hi));
    return r;
}
__device__ __forceinline__ unsigned long long fma2(
    unsigned long long a, unsigned long long b, unsigned long long c) {
    unsigned long long d;
    asm("fma.rn.f32x2 %0, %1, %2, %3;" : "=l"(d) : "l"(a), "l"(b), "l"(c));
    return d;
}
__device__ __forceinline__ void unpack2(unsigned long long p, float& lo, float& hi) {
    asm("mov.b64 {%0, %1}, %2;" : "=f"(lo), "=f"(hi) : "l"(p));
}

// ---------------- merged projection GEMM (f32x2 inner) ----------------
// blocks 0..63   : qp  (16 m-tiles x 4 h-tiles), row-major out + b1
// blocks 64..575 : kp  (128 m-tiles x 4 h-tiles), transposed out
__global__ __launch_bounds__(256) void proj_kernel(
    const float* __restrict__ q, const float* __restrict__ k,
    const float* __restrict__ W1, const float* __restrict__ b1)
{
    __shared__ __align__(16) float Xs[32][68];
    __shared__ __align__(16) float Ws[32][68];

    const int bid = blockIdx.x;
    const bool isK = (bid >= 64);
    const int rb = isK ? bid - 64 : bid;
    const int m0 = (rb >> 2) * 64;
    const int h0 = (rb & 3) * 64;
    const float* __restrict__ X = isK ? k : q;
    const int colOff = isK ? 256 : 0;

    const int tid = threadIdx.x;
    const int tx = tid & 15, ty = tid >> 4;
    const int tx4 = tx * 4, ty4 = ty * 4;

    // acc pairs: [row r][col pair cp] -> (c=2cp, c=2cp+1)
    unsigned long long acc2[4][2];
#pragma unroll
    for (int r = 0; r < 4; r++) {
        acc2[r][0] = 0ull;
        acc2[r][1] = 0ull;
    }

    for (int k0 = 0; k0 < 256; k0 += 32) {
#pragma unroll
        for (int l = 0; l < 2; l++) {
            int f = tid + l * 256;
            int r = f >> 3;
            int c = (f & 7) << 2;
            float4 xv = *(const float4*)(X + (size_t)(m0 + r) * 256 + k0 + c);
            Xs[c + 0][r] = xv.x; Xs[c + 1][r] = xv.y;
            Xs[c + 2][r] = xv.z; Xs[c + 3][r] = xv.w;
            float4 wv = *(const float4*)(W1 + (size_t)(h0 + r) * 512 + colOff + k0 + c);
            Ws[c + 0][r] = wv.x; Ws[c + 1][r] = wv.y;
            Ws[c + 2][r] = wv.z; Ws[c + 3][r] = wv.w;
        }
        __syncthreads();
#pragma unroll
        for (int kk = 0; kk < 32; kk++) {
            float4 a = *(const float4*)&Xs[kk][ty4];
            float4 bb = *(const float4*)&Ws[kk][tx4];
            unsigned long long b01 = pack2(bb.x, bb.y);
            unsigned long long b23 = pack2(bb.z, bb.w);
            unsigned long long a0 = pack2(a.x, a.x);
            unsigned long long a1 = pack2(a.y, a.y);
            unsigned long long a2 = pack2(a.z, a.z);
            unsigned long long a3 = pack2(a.w, a.w);
            acc2[0][0] = fma2(a0, b01, acc2[0][0]);
            acc2[0][1] = fma2(a0, b23, acc2[0][1]);
            acc2[1][0] = fma2(a1, b01, acc2[1][0]);
            acc2[1][1] = fma2(a1, b23, acc2[1][1]);
            acc2[2][0] = fma2(a2, b01, acc2[2][0]);
            acc2[2][1] = fma2(a2, b23, acc2[2][1]);
            acc2[3][0] = fma2(a3, b01, acc2[3][0]);
            acc2[3][1] = fma2(a3, b23, acc2[3][1]);
        }
        __syncthreads();
    }

    // unpack
    float acc[4][4];
#pragma unroll
    for (int r = 0; r < 4; r++) {
        unpack2(acc2[r][0], acc[r][0], acc[r][1]);
        unpack2(acc2[r][1], acc[r][2], acc[r][3]);
    }

    if (!isK) {
#pragma unroll
        for (int r = 0; r < 4; r++) {
            float4 ov;
            ov.x = acc[r][0] + b1[h0 + tx4 + 0];
            ov.y = acc[r][1] + b1[h0 + tx4 + 1];
            ov.z = acc[r][2] + b1[h0 + tx4 + 2];
            ov.w = acc[r][3] + b1[h0 + tx4 + 3];
            *(float4*)(g_qp + (size_t)(m0 + ty4 + r) * 256 + h0 + tx4) = ov;
        }
    } else {
        const int b = m0 >> 9;
        const int i0 = (m0 & 511) + ty4;
#pragma unroll
        for (int c = 0; c < 4; c++) {
            int h = h0 + tx4 + c;
            float4 ov = make_float4(acc[0][c], acc[1][c], acc[2][c], acc[3][c]);
            *(float4*)(g_kpt + ((size_t)(b * 256 + h) << 9) + i0) = ov;
        }
    }
}

// ---------------- hardware tanh (MUFU.TANH) ----------------
__device__ __forceinline__ float tanh_fast(float x)
{
    float y;
    asm("tanh.approx.f32 %0, %1;" : "=f"(y) : "f"(x));
    return y;
}

// ---------------- score kernel: grid 1024 = b(16) x o-group(16) x i-chunk(4) ----
__global__ __launch_bounds__(128) void score_kernel(const float* __restrict__ W2)
{
    __shared__ __align__(16) float s_qp[SOB][D_];
    __shared__ __align__(16) float s_w2[D_];

    const int bx = blockIdx.x;
    const int b  = bx >> 6;
    const int og = (bx >> 2) & 15;
    const int ic = bx & 3;
    const int o0 = og << 2;
    const int tid = threadIdx.x;

    {
        const float4* src = (const float4*)(g_qp + ((size_t)(b * O_ + o0) << 8));
        ((float4*)s_qp)[tid]       = src[tid];
        ((float4*)s_qp)[tid + 128] = src[tid + 128];
        if (tid < 64) ((float4*)s_w2)[tid] = ((const float4*)W2)[tid];
    }
    __syncthreads();

    const int i = (ic << 7) + tid;
    const float* kpt = g_kpt + ((size_t)b << 17) + i;

    float a0 = 0.f, a1 = 0.f, a2 = 0.f, a3 = 0.f;
    for (int h = 0; h < D_; h += 8) {
        float kv[8];
#pragma unroll
        for (int j = 0; j < 8; j++)
            kv[j] = kpt[(size_t)(h + j) << 9];
#pragma unroll
        for (int j = 0; j < 8; j++) {
            const float w = s_w2[h + j];
            a0 = fmaf(tanh_fast(s_qp[0][h + j] + kv[j]), w, a0);
            a1 = fmaf(tanh_fast(s_qp[1][h + j] + kv[j]), w, a1);
            a2 = fmaf(tanh_fast(s_qp[2][h + j] + kv[j]), w, a2);
            a3 = fmaf(tanh_fast(s_qp[3][h + j] + kv[j]), w, a3);
        }
    }
    float* dst = g_sc + ((size_t)(b * O_ + o0) << 9) + i;
    dst[0 << 9] = a0;
    dst[1 << 9] = a1;
    dst[2 << 9] = a2;
    dst[3 << 9] = a3;
}

// ---------------- finish kernel: softmax + attn@v + Wf. grid 128, 512 threads ----
__global__ __launch_bounds__(512) void finish_kernel(
    const float* __restrict__ v, const int* __restrict__ mask,
    const float* __restrict__ Wf, const float* __restrict__ bf,
    float* __restrict__ out, float* __restrict__ attn_out)
{
    __shared__ __align__(16) float s_p[OPB][I_];        // 16KB
    __shared__ __align__(16) float s_part[2][OPB][D_];  // 16KB
    __shared__ __align__(16) float s_pre[OPB][D_];      // 8KB
    __shared__ float s_redA[OPB][16];
    __shared__ float s_redB[OPB][16];

    const int b  = blockIdx.x >> 3;
    const int o0 = (blockIdx.x & 7) << 3;
    const int tid = threadIdx.x;
    const int lane = tid & 31;
    const int warp = tid >> 5;      // 0..15

    // ---- softmax over i (tid = i, 8 o's) ----
    const int msk = mask[b * I_ + tid];
    const float* scp = g_sc + ((size_t)(b * O_ + o0) << 9) + tid;
    float sc[OPB], e[OPB];
#pragma unroll
    for (int oo = 0; oo < OPB; oo++) {
        sc[oo] = msk ? -1e30f : scp[(size_t)oo << 9];
        float m = sc[oo];
#pragma unroll
        for (int off = 16; off > 0; off >>= 1)
            m = fmaxf(m, __shfl_xor_sync(0xffffffffu, m, off));
        if (lane == 0) s_redA[oo][warp] = m;
    }
    __syncthreads();
#pragma unroll
    for (int oo = 0; oo < OPB; oo++) {
        float mx = s_redA[oo][0];
#pragma unroll
        for (int j = 1; j < 16; j++) mx = fmaxf(mx, s_redA[oo][j]);
        e[oo] = __expf(sc[oo] - mx);
        float ssum = e[oo];
#pragma unroll
        for (int off = 16; off > 0; off >>= 1)
            ssum += __shfl_xor_sync(0xffffffffu, ssum, off);
        if (lane == 0) s_redB[oo][warp] = ssum;
    }
    __syncthreads();
#pragma unroll
    for (int oo = 0; oo < OPB; oo++) {
        float tot = 0.f;
#pragma unroll
        for (int j = 0; j < 16; j++) tot += s_redB[oo][j];
        const float p = e[oo] * __fdividef(1.0f, tot);
        s_p[oo][tid] = p;
        attn_out[((size_t)(b * O_ + o0 + oo) << 9) + tid] = p;
    }
    __syncthreads();

    // ---- pre = attn @ v, i-range split across thread halves, 8 o's ----
    {
        const int half = tid >> 8;      // 0/1
        const int d = tid & 255;
        const float* vb = v + ((size_t)b << 17) + ((size_t)half << 16) + d;
        float ac[OPB];
#pragma unroll
        for (int oo = 0; oo < OPB; oo++) ac[oo] = 0.f;
#pragma unroll 2
        for (int ii = 0; ii < 256; ii += 4) {
            const int i = (half << 8) + ii;
            float v0 = vb[(ii + 0) << 8];
            float v1 = vb[(ii + 1) << 8];
            float v2 = vb[(ii + 2) << 8];
            float v3 = vb[(ii + 3) << 8];
#pragma unroll
            for (int oo = 0; oo < OPB; oo++) {
                float4 p = *(const float4*)&s_p[oo][i];
                ac[oo] = fmaf(p.x, v0, ac[oo]);
                ac[oo] = fmaf(p.y, v1, ac[oo]);
                ac[oo] = fmaf(p.z, v2, ac[oo]);
                ac[oo] = fmaf(p.w, v3, ac[oo]);
            }
        }
#pragma unroll
        for (int oo = 0; oo < OPB; oo++)
            s_part[half][oo][d] = ac[oo];
    }
    __syncthreads();
    if (tid < 256) {
#pragma unroll
        for (int oo = 0; oo < OPB; oo++)
            s_pre[oo][tid] = s_part[0][oo][tid] + s_part[1][oo][tid];
    }
    __syncthreads();

    // ---- out = leaky(pre @ Wf^T + bf): thread = (d, o-quad), shuffle-free ----
    {
        const int d = tid & 255;
        const int oq = (tid >> 8) << 2;      // 0 or 4
        const float* wfrow = Wf + ((size_t)d << 8);
        float acc[4] = {0.f, 0.f, 0.f, 0.f};
#pragma unroll 4
        for (int h = 0; h < D_; h += 4) {
            float4 w = *(const float4*)(wfrow + h);
#pragma unroll
            for (int j = 0; j < 4; j++) {
                float4 pp = *(const float4*)&s_pre[oq + j][h];
                acc[j] = fmaf(pp.x, w.x, acc[j]);
                acc[j] = fmaf(pp.y, w.y, acc[j]);
                acc[j] = fmaf(pp.z, w.z, acc[j]);
                acc[j] = fmaf(pp.w, w.w, acc[j]);
            }
        }
        const float bfd = bf[d];
#pragma unroll
        for (int j = 0; j < 4; j++) {
            float f = acc[j] + bfd;
            f = (f >= 0.f) ? f : 0.01f * f;
            out[((size_t)(b * O_ + o0 + oq + j) << 8) + d] = f;
        }
    }
}

// ---------------- launch ----------------
extern "C" void kernel_launch(void* const* d_in, const int* in_sizes, int n_in,
                              void* d_out, int out_size)
{
    const float* q  = (const float*)d_in[0];
    const float* k  = (const float*)d_in[1];
    const float* v  = (const float*)d_in[2];
    const int* mask = (const int*)d_in[3];
    const float* W1 = (const float*)d_in[4];
    const float* b1 = (const float*)d_in[5];
    const float* W2 = (const float*)d_in[6];
    // b2 (d_in[7]) cancels in softmax
    const float* Wf = (const float*)d_in[8];
    const float* bf = (const float*)d_in[9];

    float* out  = (float*)d_out;                  // (16,64,256)
    float* attn = out + (size_t)B_ * O_ * D_;     // (16,64,512)

    proj_kernel<<<576, 256>>>(q, k, W1, b1);
    score_kernel<<<1024, 128>>>(W2);
    finish_kernel<<<128, 512>>>(v, mask, Wf, bf, out, attn);
}

// round 6
// speedup vs baseline: 1.0235x; 1.0235x over previous
#include <cuda_runtime.h>
#include <cstdint>

#define B_ 16
#define O_ 64
#define I_ 512
#define D_ 256
#define OPB 4    // o-values per finish block
#define SOB 4    // o-values per score block

// ---------------- scratch (no allocation allowed) ----------------
__device__ float g_qp[B_ * O_ * D_];    // [b][o][h]  qp' = q@W1q^T + b1
__device__ float g_kpt[B_ * D_ * I_];   // [b][h][i]  kp^T
__device__ float g_sc[B_ * O_ * I_];    // [b][o][i]  raw scores

// ---------------- merged projection GEMM, double-buffered ----------------
// blocks 0..63   : qp  (16 m-tiles x 4 h-tiles), row-major out + b1
// blocks 64..575 : kp  (128 m-tiles x 4 h-tiles), transposed out
__global__ __launch_bounds__(256) void proj_kernel(
    const float* __restrict__ q, const float* __restrict__ k,
    const float* __restrict__ W1, const float* __restrict__ b1)
{
    __shared__ __align__(16) float Xs[2][32][68];
    __shared__ __align__(16) float Ws[2][32][68];

    const int bid = blockIdx.x;
    const bool isK = (bid >= 64);
    const int rb = isK ? bid - 64 : bid;
    const int m0 = (rb >> 2) * 64;
    const int h0 = (rb & 3) * 64;
    const float* __restrict__ X = isK ? k : q;
    const int colOff = isK ? 256 : 0;

    const int tid = threadIdx.x;
    const int tx = tid & 15, ty = tid >> 4;
    const int tx4 = tx * 4, ty4 = ty * 4;

    // load indices (fixed per thread): two (row, col4) pairs
    const int r0 = tid >> 3;
    const int c0 = (tid & 7) << 2;
    const int r1 = (tid + 256) >> 3;
    const int c1 = ((tid + 256) & 7) << 2;

    float acc[4][4];
#pragma unroll
    for (int r = 0; r < 4; r++)
#pragma unroll
        for (int c = 0; c < 4; c++) acc[r][c] = 0.f;

    // prologue: tile 0 -> buffer 0
    {
        float4 xv0 = *(const float4*)(X + (size_t)(m0 + r0) * 256 + c0);
        float4 wv0 = *(const float4*)(W1 + (size_t)(h0 + r0) * 512 + colOff + c0);
        float4 xv1 = *(const float4*)(X + (size_t)(m0 + r1) * 256 + c1);
        float4 wv1 = *(const float4*)(W1 + (size_t)(h0 + r1) * 512 + colOff + c1);
        Xs[0][c0 + 0][r0] = xv0.x; Xs[0][c0 + 1][r0] = xv0.y;
        Xs[0][c0 + 2][r0] = xv0.z; Xs[0][c0 + 3][r0] = xv0.w;
        Ws[0][c0 + 0][r0] = wv0.x; Ws[0][c0 + 1][r0] = wv0.y;
        Ws[0][c0 + 2][r0] = wv0.z; Ws[0][c0 + 3][r0] = wv0.w;
        Xs[0][c1 + 0][r1] = xv1.x; Xs[0][c1 + 1][r1] = xv1.y;
        Xs[0][c1 + 2][r1] = xv1.z; Xs[0][c1 + 3][r1] = xv1.w;
        Ws[0][c1 + 0][r1] = wv1.x; Ws[0][c1 + 1][r1] = wv1.y;
        Ws[0][c1 + 2][r1] = wv1.z; Ws[0][c1 + 3][r1] = wv1.w;
    }
    __syncthreads();

#pragma unroll
    for (int t = 0; t < 8; t++) {
        const int cur = t & 1;
        float4 xv0, wv0, xv1, wv1;
        if (t < 7) {
            const int kn = (t + 1) << 5;
            xv0 = *(const float4*)(X + (size_t)(m0 + r0) * 256 + kn + c0);
            wv0 = *(const float4*)(W1 + (size_t)(h0 + r0) * 512 + colOff + kn + c0);
            xv1 = *(const float4*)(X + (size_t)(m0 + r1) * 256 + kn + c1);
            wv1 = *(const float4*)(W1 + (size_t)(h0 + r1) * 512 + colOff + kn + c1);
        }
#pragma unroll
        for (int kk = 0; kk < 32; kk++) {
            float4 a = *(const float4*)&Xs[cur][kk][ty4];
            float4 bb = *(const float4*)&Ws[cur][kk][tx4];
            float av[4] = {a.x, a.y, a.z, a.w};
            float bv[4] = {bb.x, bb.y, bb.z, bb.w};
#pragma unroll
            for (int r = 0; r < 4; r++)
#pragma unroll
                for (int c = 0; c < 4; c++)
                    acc[r][c] = fmaf(av[r], bv[c], acc[r][c]);
        }
        if (t < 7) {
            const int nxt = cur ^ 1;
            Xs[nxt][c0 + 0][r0] = xv0.x; Xs[nxt][c0 + 1][r0] = xv0.y;
            Xs[nxt][c0 + 2][r0] = xv0.z; Xs[nxt][c0 + 3][r0] = xv0.w;
            Ws[nxt][c0 + 0][r0] = wv0.x; Ws[nxt][c0 + 1][r0] = wv0.y;
            Ws[nxt][c0 + 2][r0] = wv0.z; Ws[nxt][c0 + 3][r0] = wv0.w;
            Xs[nxt][c1 + 0][r1] = xv1.x; Xs[nxt][c1 + 1][r1] = xv1.y;
            Xs[nxt][c1 + 2][r1] = xv1.z; Xs[nxt][c1 + 3][r1] = xv1.w;
            Ws[nxt][c1 + 0][r1] = wv1.x; Ws[nxt][c1 + 1][r1] = wv1.y;
            Ws[nxt][c1 + 2][r1] = wv1.z; Ws[nxt][c1 + 3][r1] = wv1.w;
        }
        __syncthreads();
    }

    if (!isK) {
#pragma unroll
        for (int r = 0; r < 4; r++) {
            float4 ov;
            ov.x = acc[r][0] + b1[h0 + tx4 + 0];
            ov.y = acc[r][1] + b1[h0 + tx4 + 1];
            ov.z = acc[r][2] + b1[h0 + tx4 + 2];
            ov.w = acc[r][3] + b1[h0 + tx4 + 3];
            *(float4*)(g_qp + (size_t)(m0 + ty4 + r) * 256 + h0 + tx4) = ov;
        }
    } else {
        const int b = m0 >> 9;
        const int i0 = (m0 & 511) + ty4;
#pragma unroll
        for (int c = 0; c < 4; c++) {
            int h = h0 + tx4 + c;
            float4 ov = make_float4(acc[0][c], acc[1][c], acc[2][c], acc[3][c]);
            *(float4*)(g_kpt + ((size_t)(b * 256 + h) << 9) + i0) = ov;
        }
    }
}

// ---------------- hardware tanh (MUFU.TANH) ----------------
__device__ __forceinline__ float tanh_fast(float x)
{
    float y;
    asm("tanh.approx.f32 %0, %1;" : "=f"(y) : "f"(x));
    return y;
}

// ---------------- score kernel: grid 1024 = b(16) x o-group(16) x i-chunk(4) ----
__global__ __launch_bounds__(128) void score_kernel(const float* __restrict__ W2)
{
    __shared__ __align__(16) float s_qp[SOB][D_];
    __shared__ __align__(16) float s_w2[D_];

    const int bx = blockIdx.x;
    const int b  = bx >> 6;
    const int og = (bx >> 2) & 15;
    const int ic = bx & 3;
    const int o0 = og << 2;
    const int tid = threadIdx.x;

    {
        const float4* src = (const float4*)(g_qp + ((size_t)(b * O_ + o0) << 8));
        ((float4*)s_qp)[tid]       = src[tid];
        ((float4*)s_qp)[tid + 128] = src[tid + 128];
        if (tid < 64) ((float4*)s_w2)[tid] = ((const float4*)W2)[tid];
    }
    __syncthreads();

    const int i = (ic << 7) + tid;
    const float* kpt = g_kpt + ((size_t)b << 17) + i;

    float a0 = 0.f, a1 = 0.f, a2 = 0.f, a3 = 0.f;
    for (int h = 0; h < D_; h += 8) {
        float kv[8];
#pragma unroll
        for (int j = 0; j < 8; j++)
            kv[j] = kpt[(size_t)(h + j) << 9];
#pragma unroll
        for (int j = 0; j < 8; j++) {
            const float w = s_w2[h + j];
            a0 = fmaf(tanh_fast(s_qp[0][h + j] + kv[j]), w, a0);
            a1 = fmaf(tanh_fast(s_qp[1][h + j] + kv[j]), w, a1);
            a2 = fmaf(tanh_fast(s_qp[2][h + j] + kv[j]), w, a2);
            a3 = fmaf(tanh_fast(s_qp[3][h + j] + kv[j]), w, a3);
        }
    }
    float* dst = g_sc + ((size_t)(b * O_ + o0) << 9) + i;
    dst[0 << 9] = a0;
    dst[1 << 9] = a1;
    dst[2 << 9] = a2;
    dst[3 << 9] = a3;
}

// ---------------- finish kernel: softmax + attn@v + Wf. grid 256, 512 threads ----
__global__ __launch_bounds__(512) void finish_kernel(
    const float* __restrict__ v, const int* __restrict__ mask,
    const float* __restrict__ Wf, const float* __restrict__ bf,
    float* __restrict__ out, float* __restrict__ attn_out)
{
    __shared__ __align__(16) float s_p[OPB][I_];        // 8KB
    __shared__ __align__(16) float s_part[2][OPB][D_];  // 8KB
    __shared__ __align__(16) float s_pre[OPB][D_];      // 4KB
    __shared__ float s_redA[OPB][16];
    __shared__ float s_redB[OPB][16];

    const int b  = blockIdx.x >> 4;
    const int o0 = (blockIdx.x & 15) << 2;
    const int tid = threadIdx.x;
    const int lane = tid & 31;
    const int warp = tid >> 5;      // 0..15

    // ---- softmax over i (tid = i) ----
    const int msk = mask[b * I_ + tid];
    const float* scp = g_sc + ((size_t)(b * O_ + o0) << 9) + tid;
    float sc[OPB], e[OPB];
#pragma unroll
    for (int oo = 0; oo < OPB; oo++) {
        sc[oo] = msk ? -1e30f : scp[(size_t)oo << 9];
        float m = sc[oo];
#pragma unroll
        for (int off = 16; off > 0; off >>= 1)
            m = fmaxf(m, __shfl_xor_sync(0xffffffffu, m, off));
        if (lane == 0) s_redA[oo][warp] = m;
    }
    __syncthreads();
#pragma unroll
    for (int oo = 0; oo < OPB; oo++) {
        float mx = s_redA[oo][0];
#pragma unroll
        for (int j = 1; j < 16; j++) mx = fmaxf(mx, s_redA[oo][j]);
        e[oo] = __expf(sc[oo] - mx);
        float ssum = e[oo];
#pragma unroll
        for (int off = 16; off > 0; off >>= 1)
            ssum += __shfl_xor_sync(0xffffffffu, ssum, off);
        if (lane == 0) s_redB[oo][warp] = ssum;
    }
    __syncthreads();
#pragma unroll
    for (int oo = 0; oo < OPB; oo++) {
        float tot = 0.f;
#pragma unroll
        for (int j = 0; j < 16; j++) tot += s_redB[oo][j];
        const float p = e[oo] * __fdividef(1.0f, tot);
        s_p[oo][tid] = p;
        attn_out[((size_t)(b * O_ + o0 + oo) << 9) + tid] = p;
    }
    __syncthreads();

    // ---- pre = attn @ v, i-range split across thread halves ----
    {
        const int half = tid >> 8;      // 0/1
        const int d = tid & 255;
        const float* vb = v + ((size_t)b << 17) + ((size_t)half << 16) + d;
        float ac0 = 0.f, ac1 = 0.f, ac2 = 0.f, ac3 = 0.f;
#pragma unroll 2
        for (int ii = 0; ii < 256; ii += 4) {
            const int i = (half << 8) + ii;
            float4 p0 = *(const float4*)&s_p[0][i];
            float4 p1 = *(const float4*)&s_p[1][i];
            float4 p2 = *(const float4*)&s_p[2][i];
            float4 p3 = *(const float4*)&s_p[3][i];
            float v0 = vb[(ii + 0) << 8];
            float v1 = vb[(ii + 1) << 8];
            float v2 = vb[(ii + 2) << 8];
            float v3 = vb[(ii + 3) << 8];
            ac0 = fmaf(p0.x, v0, ac0); ac1 = fmaf(p1.x, v0, ac1);
            ac2 = fmaf(p2.x, v0, ac2); ac3 = fmaf(p3.x, v0, ac3);
            ac0 = fmaf(p0.y, v1, ac0); ac1 = fmaf(p1.y, v1, ac1);
            ac2 = fmaf(p2.y, v1, ac2); ac3 = fmaf(p3.y, v1, ac3);
            ac0 = fmaf(p0.z, v2, ac0); ac1 = fmaf(p1.z, v2, ac1);
            ac2 = fmaf(p2.z, v2, ac2); ac3 = fmaf(p3.z, v2, ac3);
            ac0 = fmaf(p0.w, v3, ac0); ac1 = fmaf(p1.w, v3, ac1);
            ac2 = fmaf(p2.w, v3, ac2); ac3 = fmaf(p3.w, v3, ac3);
        }
        s_part[half][0][d] = ac0;
        s_part[half][1][d] = ac1;
        s_part[half][2][d] = ac2;
        s_part[half][3][d] = ac3;
    }
    __syncthreads();
    if (tid < 256) {
#pragma unroll
        for (int oo = 0; oo < OPB; oo++)
            s_pre[oo][tid] = s_part[0][oo][tid] + s_part[1][oo][tid];
    }
    __syncthreads();

    // ---- out = leaky(pre @ Wf^T + bf): thread = (d, h-half), shuffle-free,
    //      Wf read exactly once per block ----
    {
        const int d  = tid & 255;
        const int hh = tid >> 8;            // 0/1
        const float* wfrow = Wf + ((size_t)d << 8) + (hh << 7);
        float acc[4] = {0.f, 0.f, 0.f, 0.f};
#pragma unroll 4
        for (int h = 0; h < 128; h += 4) {
            float4 w = *(const float4*)(wfrow + h);
#pragma unroll
            for (int j = 0; j < 4; j++) {
                const float4 pp = *(const float4*)&s_pre[j][(hh << 7) + h];
                acc[j] = fmaf(pp.x, w.x, acc[j]);
                acc[j] = fmaf(pp.y, w.y, acc[j]);
                acc[j] = fmaf(pp.z, w.z, acc[j]);
                acc[j] = fmaf(pp.w, w.w, acc[j]);
            }
        }
#pragma unroll
        for (int j = 0; j < 4; j++)
            s_part[hh][j][d] = acc[j];
    }
    __syncthreads();
    if (tid < 256) {
        const float bfd = bf[tid];
#pragma unroll
        for (int j = 0; j < 4; j++) {
            float f = s_part[0][j][tid] + s_part[1][j][tid] + bfd;
            f = (f >= 0.f) ? f : 0.01f * f;
            out[((size_t)(b * O_ + o0 + j) << 8) + tid] = f;
        }
    }
}

// ---------------- launch ----------------
extern "C" void kernel_launch(void* const* d_in, const int* in_sizes, int n_in,
                              void* d_out, int out_size)
{
    const float* q  = (const float*)d_in[0];
    const float* k  = (const float*)d_in[1];
    const float* v  = (const float*)d_in[2];
    const int* mask = (const int*)d_in[3];
    const float* W1 = (const float*)d_in[4];
    const float* b1 = (const float*)d_in[5];
    const float* W2 = (const float*)d_in[6];
    // b2 (d_in[7]) cancels in softmax
    const float* Wf = (const float*)d_in[8];
    const float* bf = (const float*)d_in[9];

    float* out  = (float*)d_out;                  // (16,64,256)
    float* attn = out + (size_t)B_ * O_ * D_;     // (16,64,512)

    proj_kernel<<<576, 256>>>(q, k, W1, b1);
    score_kernel<<<1024, 128>>>(W2);
    finish_kernel<<<256, 512>>>(v, mask, Wf, bf, out, attn);
}

// round 8
// speedup vs baseline: 1.1496x; 1.1233x over previous
#include <cuda_runtime.h>
#include <cstdint>

#define B_ 16
#define O_ 64
#define I_ 512
#define D_ 256
#define OPB 4    // o-values per finish block
#define SOB 4    // o-values per score block

// ---------------- scratch (no allocation allowed) ----------------
__device__ float g_qp[B_ * O_ * D_];    // [b][o][h]  qp' = q@W1q^T + b1
__device__ float g_kpt[B_ * D_ * I_];   // [b][h][i]  kp^T
__device__ float g_sc[B_ * O_ * I_];    // [b][o][i]  raw scores

// ---------------- merged projection GEMM ----------------
// tile 128(m) x 64(h), Kc=32, 256 threads, 8x4 microtile, double-buffered.
// blocks 0..31   : qp  (8 m-tiles x 4 h-tiles), row-major out + b1
// blocks 32..287 : kp  (64 m-tiles x 4 h-tiles), transposed out
__global__ __launch_bounds__(256) void proj_kernel(
    const float* __restrict__ q, const float* __restrict__ k,
    const float* __restrict__ W1, const float* __restrict__ b1)
{
    __shared__ __align__(16) float Xs[2][32][132];  // [k][m], m=128 +4 pad
    __shared__ __align__(16) float Ws[2][32][68];   // [k][h], h=64 +4 pad

    const int bid = blockIdx.x;
    const bool isK = (bid >= 32);
    const int rb = isK ? bid - 32 : bid;
    const int m0 = (rb >> 2) * 128;
    const int h0 = (rb & 3) * 64;
    const float* __restrict__ X = isK ? k : q;
    const int colOff = isK ? 256 : 0;

    const int tid = threadIdx.x;
    const int tx = tid & 15;            // h dir: 16 x 4 = 64
    const int ty = tid >> 4;            // m dir: 16 x 8 = 128
    const int tx4 = tx * 4, ty8 = ty * 8;

    // X loads: 128x32 floats = 4 float4/thread. f = tid + 256*l
    // W loads: 64x32 floats = 2 float4/thread.
    const int xr[4] = { tid >> 3, (tid + 256) >> 3, (tid + 512) >> 3, (tid + 768) >> 3 };
    const int xc = (tid & 7) << 2;
    const int wr0 = tid >> 3;           // 0..31
    const int wr1 = (tid + 256) >> 3;   // 32..63
    const int wc = xc;

    float acc[8][4];
#pragma unroll
    for (int r = 0; r < 8; r++)
#pragma unroll
        for (int c = 0; c < 4; c++) acc[r][c] = 0.f;

    // prologue: tile 0 -> buffer 0
    {
        float4 xv[4], wv[2];
#pragma unroll
        for (int l = 0; l < 4; l++)
            xv[l] = *(const float4*)(X + (size_t)(m0 + xr[l]) * 256 + xc);
        wv[0] = *(const float4*)(W1 + (size_t)(h0 + wr0) * 512 + colOff + wc);
        wv[1] = *(const float4*)(W1 + (size_t)(h0 + wr1) * 512 + colOff + wc);
#pragma unroll
        for (int l = 0; l < 4; l++) {
            Xs[0][xc + 0][xr[l]] = xv[l].x; Xs[0][xc + 1][xr[l]] = xv[l].y;
            Xs[0][xc + 2][xr[l]] = xv[l].z; Xs[0][xc + 3][xr[l]] = xv[l].w;
        }
        Ws[0][wc + 0][wr0] = wv[0].x; Ws[0][wc + 1][wr0] = wv[0].y;
        Ws[0][wc + 2][wr0] = wv[0].z; Ws[0][wc + 3][wr0] = wv[0].w;
        Ws[0][wc + 0][wr1] = wv[1].x; Ws[0][wc + 1][wr1] = wv[1].y;
        Ws[0][wc + 2][wr1] = wv[1].z; Ws[0][wc + 3][wr1] = wv[1].w;
    }
    __syncthreads();

#pragma unroll
    for (int t = 0; t < 8; t++) {
        const int cur = t & 1;
        float4 xv[4], wv[2];
        if (t < 7) {
            const int kn = (t + 1) << 5;
#pragma unroll
            for (int l = 0; l < 4; l++)
                xv[l] = *(const float4*)(X + (size_t)(m0 + xr[l]) * 256 + kn + xc);
            wv[0] = *(const float4*)(W1 + (size_t)(h0 + wr0) * 512 + colOff + kn + wc);
            wv[1] = *(const float4*)(W1 + (size_t)(h0 + wr1) * 512 + colOff + kn + wc);
        }
#pragma unroll
        for (int kk = 0; kk < 32; kk++) {
            float4 a0 = *(const float4*)&Xs[cur][kk][ty8];
            float4 a1 = *(const float4*)&Xs[cur][kk][ty8 + 4];
            float4 bb = *(const float4*)&Ws[cur][kk][tx4];
            float av[8] = {a0.x, a0.y, a0.z, a0.w, a1.x, a1.y, a1.z, a1.w};
            float bv[4] = {bb.x, bb.y, bb.z, bb.w};
#pragma unroll
            for (int r = 0; r < 8; r++)
#pragma unroll
                for (int c = 0; c < 4; c++)
                    acc[r][c] = fmaf(av[r], bv[c], acc[r][c]);
        }
        if (t < 7) {
            const int nxt = cur ^ 1;
#pragma unroll
            for (int l = 0; l < 4; l++) {
                Xs[nxt][xc + 0][xr[l]] = xv[l].x; Xs[nxt][xc + 1][xr[l]] = xv[l].y;
                Xs[nxt][xc + 2][xr[l]] = xv[l].z; Xs[nxt][xc + 3][xr[l]] = xv[l].w;
            }
            Ws[nxt][wc + 0][wr0] = wv[0].x; Ws[nxt][wc + 1][wr0] = wv[0].y;
            Ws[nxt][wc + 2][wr0] = wv[0].z; Ws[nxt][wc + 3][wr0] = wv[0].w;
            Ws[nxt][wc + 0][wr1] = wv[1].x; Ws[nxt][wc + 1][wr1] = wv[1].y;
            Ws[nxt][wc + 2][wr1] = wv[1].z; Ws[nxt][wc + 3][wr1] = wv[1].w;
        }
        __syncthreads();
    }

    if (!isK) {
        const float b0 = b1[h0 + tx4 + 0];
        const float b1v = b1[h0 + tx4 + 1];
        const float b2v = b1[h0 + tx4 + 2];
        const float b3v = b1[h0 + tx4 + 3];
#pragma unroll
        for (int r = 0; r < 8; r++) {
            float4 ov;
            ov.x = acc[r][0] + b0;
            ov.y = acc[r][1] + b1v;
            ov.z = acc[r][2] + b2v;
            ov.w = acc[r][3] + b3v;
            *(float4*)(g_qp + (size_t)(m0 + ty8 + r) * 256 + h0 + tx4) = ov;
        }
    } else {
        const int b = m0 >> 9;               // 128 | 512, no batch crossing
        const int i0 = (m0 & 511) + ty8;
#pragma unroll
        for (int c = 0; c < 4; c++) {
            const int h = h0 + tx4 + c;
            float* dst = g_kpt + ((size_t)(b * 256 + h) << 9) + i0;
            *(float4*)(dst)     = make_float4(acc[0][c], acc[1][c], acc[2][c], acc[3][c]);
            *(float4*)(dst + 4) = make_float4(acc[4][c], acc[5][c], acc[6][c], acc[7][c]);
        }
    }
}

// ---------------- hardware tanh (MUFU.TANH) ----------------
__device__ __forceinline__ float tanh_fast(float x)
{
    float y;
    asm("tanh.approx.f32 %0, %1;" : "=f"(y) : "f"(x));
    return y;
}

// ---------------- score kernel: grid 1024 = b(16) x o-group(16) x i-chunk(4) ----
__global__ __launch_bounds__(128) void score_kernel(const float* __restrict__ W2)
{
    __shared__ __align__(16) float s_qp[SOB][D_];
    __shared__ __align__(16) float s_w2[D_];

    const int bx = blockIdx.x;
    const int b  = bx >> 6;
    const int og = (bx >> 2) & 15;
    const int ic = bx & 3;
    const int o0 = og << 2;
    const int tid = threadIdx.x;

    {
        const float4* src = (const float4*)(g_qp + ((size_t)(b * O_ + o0) << 8));
        ((float4*)s_qp)[tid]       = src[tid];
        ((float4*)s_qp)[tid + 128] = src[tid + 128];
        if (tid < 64) ((float4*)s_w2)[tid] = ((const float4*)W2)[tid];
    }
    __syncthreads();

    const int i = (ic << 7) + tid;
    const float* kpt = g_kpt + ((size_t)b << 17) + i;

    float a0 = 0.f, a1 = 0.f, a2 = 0.f, a3 = 0.f;
    for (int h = 0; h < D_; h += 8) {
        float kv[8];
#pragma unroll
        for (int j = 0; j < 8; j++)
            kv[j] = kpt[(size_t)(h + j) << 9];
#pragma unroll
        for (int j = 0; j < 8; j++) {
            const float w = s_w2[h + j];
            a0 = fmaf(tanh_fast(s_qp[0][h + j] + kv[j]), w, a0);
            a1 = fmaf(tanh_fast(s_qp[1][h + j] + kv[j]), w, a1);
            a2 = fmaf(tanh_fast(s_qp[2][h + j] + kv[j]), w, a2);
            a3 = fmaf(tanh_fast(s_qp[3][h + j] + kv[j]), w, a3);
        }
    }
    float* dst = g_sc + ((size_t)(b * O_ + o0) << 9) + i;
    dst[0 << 9] = a0;
    dst[1 << 9] = a1;
    dst[2 << 9] = a2;
    dst[3 << 9] = a3;
}

// ---------------- finish kernel (R4-measured-best): grid 256, 512 threads ----
__global__ __launch_bounds__(512) void finish_kernel(
    const float* __restrict__ v, const int* __restrict__ mask,
    const float* __restrict__ Wf, const float* __restrict__ bf,
    float* __restrict__ out, float* __restrict__ attn_out)
{
    __shared__ __align__(16) float s_p[OPB][I_];        // 8KB
    __shared__ __align__(16) float s_part[2][OPB][D_];  // 8KB
    __shared__ __align__(16) float s_pre[OPB][D_];      // 4KB
    __shared__ float s_redA[OPB][16];
    __shared__ float s_redB[OPB][16];

    const int b  = blockIdx.x >> 4;
    const int o0 = (blockIdx.x & 15) << 2;
    const int tid = threadIdx.x;
    const int lane = tid & 31;
    const int warp = tid >> 5;      // 0..15

    // ---- softmax over i (tid = i) ----
    const int msk = mask[b * I_ + tid];
    const float* scp = g_sc + ((size_t)(b * O_ + o0) << 9) + tid;
    float sc[OPB], e[OPB];
#pragma unroll
    for (int oo = 0; oo < OPB; oo++) {
        sc[oo] = msk ? -1e30f : scp[(size_t)oo << 9];
        float m = sc[oo];
#pragma unroll
        for (int off = 16; off > 0; off >>= 1)
            m = fmaxf(m, __shfl_xor_sync(0xffffffffu, m, off));
        if (lane == 0) s_redA[oo][warp] = m;
    }
    __syncthreads();
#pragma unroll
    for (int oo = 0; oo < OPB; oo++) {
        float mx = s_redA[oo][0];
#pragma unroll
        for (int j = 1; j < 16; j++) mx = fmaxf(mx, s_redA[oo][j]);
        e[oo] = __expf(sc[oo] - mx);
        float ssum = e[oo];
#pragma unroll
        for (int off = 16; off > 0; off >>= 1)
            ssum += __shfl_xor_sync(0xffffffffu, ssum, off);
        if (lane == 0) s_redB[oo][warp] = ssum;
    }
    __syncthreads();
#pragma unroll
    for (int oo = 0; oo < OPB; oo++) {
        float tot = 0.f;
#pragma unroll
        for (int j = 0; j < 16; j++) tot += s_redB[oo][j];
        const float p = e[oo] * __fdividef(1.0f, tot);
        s_p[oo][tid] = p;
        attn_out[((size_t)(b * O_ + o0 + oo) << 9) + tid] = p;
    }
    __syncthreads();

    // ---- pre = attn @ v, i-range split across thread halves ----
    {
        const int half = tid >> 8;      // 0/1
        const int d = tid & 255;
        const float* vb = v + ((size_t)b << 17) + ((size_t)half << 16) + d;
        float ac0 = 0.f, ac1 = 0.f, ac2 = 0.f, ac3 = 0.f;
#pragma unroll 2
        for (int ii = 0; ii < 256; ii += 4) {
            const int i = (half << 8) + ii;
            float4 p0 = *(const float4*)&s_p[0][i];
            float4 p1 = *(const float4*)&s_p[1][i];
            float4 p2 = *(const float4*)&s_p[2][i];
            float4 p3 = *(const float4*)&s_p[3][i];
            float v0 = vb[(ii + 0) << 8];
            float v1 = vb[(ii + 1) << 8];
            float v2 = vb[(ii + 2) << 8];
            float v3 = vb[(ii + 3) << 8];
            ac0 = fmaf(p0.x, v0, ac0); ac1 = fmaf(p1.x, v0, ac1);
            ac2 = fmaf(p2.x, v0, ac2); ac3 = fmaf(p3.x, v0, ac3);
            ac0 = fmaf(p0.y, v1, ac0); ac1 = fmaf(p1.y, v1, ac1);
            ac2 = fmaf(p2.y, v1, ac2); ac3 = fmaf(p3.y, v1, ac3);
            ac0 = fmaf(p0.z, v2, ac0); ac1 = fmaf(p1.z, v2, ac1);
            ac2 = fmaf(p2.z, v2, ac2); ac3 = fmaf(p3.z, v2, ac3);
            ac0 = fmaf(p0.w, v3, ac0); ac1 = fmaf(p1.w, v3, ac1);
            ac2 = fmaf(p2.w, v3, ac2); ac3 = fmaf(p3.w, v3, ac3);
        }
        s_part[half][0][d] = ac0;
        s_part[half][1][d] = ac1;
        s_part[half][2][d] = ac2;
        s_part[half][3][d] = ac3;
    }
    __syncthreads();
    if (tid < 256) {
#pragma unroll
        for (int oo = 0; oo < OPB; oo++)
            s_pre[oo][tid] = s_part[0][oo][tid] + s_part[1][oo][tid];
    }
    __syncthreads();

    // ---- out = leaky(pre @ Wf^T + bf), 16 warps x 16 d-columns each ----
    const int hb = lane * 8;
    float pr0[8], pr1[8], pr2[8], pr3[8];
#pragma unroll
    for (int j = 0; j < 8; j++) {
        pr0[j] = s_pre[0][hb + j];
        pr1[j] = s_pre[1][hb + j];
        pr2[j] = s_pre[2][hb + j];
        pr3[j] = s_pre[3][hb + j];
    }

    float ov0 = 0.f, ov1 = 0.f, ov2 = 0.f, ov3 = 0.f;
    for (int c = 0; c < 16; c++) {
        const int d = (warp << 4) + c;
        const float4* wf = (const float4*)(Wf + ((size_t)d << 8) + hb);
        float4 f0 = wf[0], f1 = wf[1];
        float fr[8] = {f0.x, f0.y, f0.z, f0.w, f1.x, f1.y, f1.z, f1.w};
        float s0 = 0.f, s1 = 0.f, s2 = 0.f, s3 = 0.f;
#pragma unroll
        for (int j = 0; j < 8; j++) {
            s0 = fmaf(pr0[j], fr[j], s0);
            s1 = fmaf(pr1[j], fr[j], s1);
            s2 = fmaf(pr2[j], fr[j], s2);
            s3 = fmaf(pr3[j], fr[j], s3);
        }
#pragma unroll
        for (int off = 16; off > 0; off >>= 1) {
            s0 += __shfl_xor_sync(0xffffffffu, s0, off);
            s1 += __shfl_xor_sync(0xffffffffu, s1, off);
            s2 += __shfl_xor_sync(0xffffffffu, s2, off);
            s3 += __shfl_xor_sync(0xffffffffu, s3, off);
        }
        if (lane == c) { ov0 = s0; ov1 = s1; ov2 = s2; ov3 = s3; }
    }
    if (lane < 16) {
        const int d = (warp << 4) + lane;
        const float bfd = bf[d];
        float f0v = ov0 + bfd; f0v = (f0v >= 0.f) ? f0v : 0.01f * f0v;
        float f1v = ov1 + bfd; f1v = (f1v >= 0.f) ? f1v : 0.01f * f1v;
        float f2v = ov2 + bfd; f2v = (f2v >= 0.f) ? f2v : 0.01f * f2v;
        float f3v = ov3 + bfd; f3v = (f3v >= 0.f) ? f3v : 0.01f * f3v;
        out[((size_t)(b * O_ + o0 + 0) << 8) + d] = f0v;
        out[((size_t)(b * O_ + o0 + 1) << 8) + d] = f1v;
        out[((size_t)(b * O_ + o0 + 2) << 8) + d] = f2v;
        out[((size_t)(b * O_ + o0 + 3) << 8) + d] = f3v;
    }
}

// ---------------- launch ----------------
extern "C" void kernel_launch(void* const* d_in, const int* in_sizes, int n_in,
                              void* d_out, int out_size)
{
    const float* q  = (const float*)d_in[0];
    const float* k  = (const float*)d_in[1];
    const float* v  = (const float*)d_in[2];
    const int* mask = (const int*)d_in[3];
    const float* W1 = (const float*)d_in[4];
    const float* b1 = (const float*)d_in[5];
    const float* W2 = (const float*)d_in[6];
    // b2 (d_in[7]) cancels in softmax
    const float* Wf = (const float*)d_in[8];
    const float* bf = (const float*)d_in[9];

    float* out  = (float*)d_out;                  // (16,64,256)
    float* attn = out + (size_t)B_ * O_ * D_;     // (16,64,512)

    proj_kernel<<<288, 256>>>(q, k, W1, b1);
    score_kernel<<<1024, 128>>>(W2);
    finish_kernel<<<256, 512>>>(v, mask, Wf, bf, out, attn);
}

// round 9
// speedup vs baseline: 1.1762x; 1.0231x over previous
#include <cuda_runtime.h>
#include <cstdint>

#define B_ 16
#define O_ 64
#define I_ 512
#define D_ 256
#define OPB 4    // o-values per finish block
#define SOB 4    // o-values per score block

// ---------------- scratch (no allocation allowed) ----------------
__device__ float g_qp[B_ * O_ * D_];    // [b][o][h]  qp' = q@W1q^T + b1
__device__ float g_kpt[B_ * D_ * I_];   // [b][h][i]  kp^T
__device__ float g_sc[B_ * O_ * I_];    // [b][o][i]  raw scores

// ---------------- merged projection GEMM ----------------
// tile 128(m) x 64(h), Kc=32, 256 threads, 8x4 microtile, SINGLE buffer.
// blocks 0..31   : qp  (8 m-tiles x 4 h-tiles), row-major out + b1
// blocks 32..287 : kp  (64 m-tiles x 4 h-tiles), transposed out
__global__ __launch_bounds__(256) void proj_kernel(
    const float* __restrict__ q, const float* __restrict__ k,
    const float* __restrict__ W1, const float* __restrict__ b1)
{
    __shared__ __align__(16) float Xs[32][132];  // [k][m], m=128 +4 pad
    __shared__ __align__(16) float Ws[32][68];   // [k][h], h=64 +4 pad

    const int bid = blockIdx.x;
    const bool isK = (bid >= 32);
    const int rb = isK ? bid - 32 : bid;
    const int m0 = (rb >> 2) * 128;
    const int h0 = (rb & 3) * 64;
    const float* __restrict__ X = isK ? k : q;
    const int colOff = isK ? 256 : 0;

    const int tid = threadIdx.x;
    const int tx = tid & 15;            // h dir: 16 x 4 = 64
    const int ty = tid >> 4;            // m dir: 16 x 8 = 128
    const int tx4 = tx * 4, ty8 = ty * 8;

    // X loads: 128x32 floats = 4 float4/thread; W loads: 64x32 = 2 float4/thread
    const int xr0 = tid >> 3;
    const int xc  = (tid & 7) << 2;
    const int wr0 = tid >> 3;           // 0..31
    const int wr1 = wr0 + 32;           // 32..63

    float acc[8][4];
#pragma unroll
    for (int r = 0; r < 8; r++)
#pragma unroll
        for (int c = 0; c < 4; c++) acc[r][c] = 0.f;

    for (int k0 = 0; k0 < 256; k0 += 32) {
#pragma unroll
        for (int l = 0; l < 4; l++) {
            const int r = xr0 + (l << 5);
            float4 xv = *(const float4*)(X + (size_t)(m0 + r) * 256 + k0 + xc);
            Xs[xc + 0][r] = xv.x; Xs[xc + 1][r] = xv.y;
            Xs[xc + 2][r] = xv.z; Xs[xc + 3][r] = xv.w;
        }
        {
            float4 wv0 = *(const float4*)(W1 + (size_t)(h0 + wr0) * 512 + colOff + k0 + xc);
            float4 wv1 = *(const float4*)(W1 + (size_t)(h0 + wr1) * 512 + colOff + k0 + xc);
            Ws[xc + 0][wr0] = wv0.x; Ws[xc + 1][wr0] = wv0.y;
            Ws[xc + 2][wr0] = wv0.z; Ws[xc + 3][wr0] = wv0.w;
            Ws[xc + 0][wr1] = wv1.x; Ws[xc + 1][wr1] = wv1.y;
            Ws[xc + 2][wr1] = wv1.z; Ws[xc + 3][wr1] = wv1.w;
        }
        __syncthreads();
#pragma unroll
        for (int kk = 0; kk < 32; kk++) {
            float4 a0 = *(const float4*)&Xs[kk][ty8];
            float4 a1 = *(const float4*)&Xs[kk][ty8 + 4];
            float4 bb = *(const float4*)&Ws[kk][tx4];
            float av[8] = {a0.x, a0.y, a0.z, a0.w, a1.x, a1.y, a1.z, a1.w};
            float bv[4] = {bb.x, bb.y, bb.z, bb.w};
#pragma unroll
            for (int r = 0; r < 8; r++)
#pragma unroll
                for (int c = 0; c < 4; c++)
                    acc[r][c] = fmaf(av[r], bv[c], acc[r][c]);
        }
        __syncthreads();
    }

    if (!isK) {
        const float b0 = b1[h0 + tx4 + 0];
        const float b1v = b1[h0 + tx4 + 1];
        const float b2v = b1[h0 + tx4 + 2];
        const float b3v = b1[h0 + tx4 + 3];
#pragma unroll
        for (int r = 0; r < 8; r++) {
            float4 ov;
            ov.x = acc[r][0] + b0;
            ov.y = acc[r][1] + b1v;
            ov.z = acc[r][2] + b2v;
            ov.w = acc[r][3] + b3v;
            *(float4*)(g_qp + (size_t)(m0 + ty8 + r) * 256 + h0 + tx4) = ov;
        }
    } else {
        const int b = m0 >> 9;               // tile never crosses batch
        const int i0 = (m0 & 511) + ty8;
#pragma unroll
        for (int c = 0; c < 4; c++) {
            const int h = h0 + tx4 + c;
            float* dst = g_kpt + ((size_t)(b * 256 + h) << 9) + i0;
            *(float4*)(dst)     = make_float4(acc[0][c], acc[1][c], acc[2][c], acc[3][c]);
            *(float4*)(dst + 4) = make_float4(acc[4][c], acc[5][c], acc[6][c], acc[7][c]);
        }
    }
}

// ---------------- hardware tanh (MUFU.TANH) ----------------
__device__ __forceinline__ float tanh_fast(float x)
{
    float y;
    asm("tanh.approx.f32 %0, %1;" : "=f"(y) : "f"(x));
    return y;
}

// ---------------- score kernel: grid 1024 = b(16) x o-group(16) x i-chunk(4) ----
__global__ __launch_bounds__(128) void score_kernel(const float* __restrict__ W2)
{
    __shared__ __align__(16) float s_qp[SOB][D_];
    __shared__ __align__(16) float s_w2[D_];

    const int bx = blockIdx.x;
    const int b  = bx >> 6;
    const int og = (bx >> 2) & 15;
    const int ic = bx & 3;
    const int o0 = og << 2;
    const int tid = threadIdx.x;

    {
        const float4* src = (const float4*)(g_qp + ((size_t)(b * O_ + o0) << 8));
        ((float4*)s_qp)[tid]       = src[tid];
        ((float4*)s_qp)[tid + 128] = src[tid + 128];
        if (tid < 64) ((float4*)s_w2)[tid] = ((const float4*)W2)[tid];
    }
    __syncthreads();

    const int i = (ic << 7) + tid;
    const float* kpt = g_kpt + ((size_t)b << 17) + i;

    float a0 = 0.f, a1 = 0.f, a2 = 0.f, a3 = 0.f;
    for (int h = 0; h < D_; h += 8) {
        float kv[8];
#pragma unroll
        for (int j = 0; j < 8; j++)
            kv[j] = kpt[(size_t)(h + j) << 9];
#pragma unroll
        for (int j = 0; j < 8; j++) {
            const float w = s_w2[h + j];
            a0 = fmaf(tanh_fast(s_qp[0][h + j] + kv[j]), w, a0);
            a1 = fmaf(tanh_fast(s_qp[1][h + j] + kv[j]), w, a1);
            a2 = fmaf(tanh_fast(s_qp[2][h + j] + kv[j]), w, a2);
            a3 = fmaf(tanh_fast(s_qp[3][h + j] + kv[j]), w, a3);
        }
    }
    float* dst = g_sc + ((size_t)(b * O_ + o0) << 9) + i;
    dst[0 << 9] = a0;
    dst[1 << 9] = a1;
    dst[2 << 9] = a2;
    dst[3 << 9] = a3;
}

// ---------------- finish kernel (R4-measured-best): grid 256, 512 threads ----
__global__ __launch_bounds__(512) void finish_kernel(
    const float* __restrict__ v, const int* __restrict__ mask,
    const float* __restrict__ Wf, const float* __restrict__ bf,
    float* __restrict__ out, float* __restrict__ attn_out)
{
    __shared__ __align__(16) float s_p[OPB][I_];        // 8KB
    __shared__ __align__(16) float s_part[2][OPB][D_];  // 8KB
    __shared__ __align__(16) float s_pre[OPB][D_];      // 4KB
    __shared__ float s_redA[OPB][16];
    __shared__ float s_redB[OPB][16];

    const int b  = blockIdx.x >> 4;
    const int o0 = (blockIdx.x & 15) << 2;
    const int tid = threadIdx.x;
    const int lane = tid & 31;
    const int warp = tid >> 5;      // 0..15

    // ---- softmax over i (tid = i) ----
    const int msk = mask[b * I_ + tid];
    const float* scp = g_sc + ((size_t)(b * O_ + o0) << 9) + tid;
    float sc[OPB], e[OPB];
#pragma unroll
    for (int oo = 0; oo < OPB; oo++) {
        sc[oo] = msk ? -1e30f : scp[(size_t)oo << 9];
        float m = sc[oo];
#pragma unroll
        for (int off = 16; off > 0; off >>= 1)
            m = fmaxf(m, __shfl_xor_sync(0xffffffffu, m, off));
        if (lane == 0) s_redA[oo][warp] = m;
    }
    __syncthreads();
#pragma unroll
    for (int oo = 0; oo < OPB; oo++) {
        float mx = s_redA[oo][0];
#pragma unroll
        for (int j = 1; j < 16; j++) mx = fmaxf(mx, s_redA[oo][j]);
        e[oo] = __expf(sc[oo] - mx);
        float ssum = e[oo];
#pragma unroll
        for (int off = 16; off > 0; off >>= 1)
            ssum += __shfl_xor_sync(0xffffffffu, ssum, off);
        if (lane == 0) s_redB[oo][warp] = ssum;
    }
    __syncthreads();
#pragma unroll
    for (int oo = 0; oo < OPB; oo++) {
        float tot = 0.f;
#pragma unroll
        for (int j = 0; j < 16; j++) tot += s_redB[oo][j];
        const float p = e[oo] * __fdividef(1.0f, tot);
        s_p[oo][tid] = p;
        attn_out[((size_t)(b * O_ + o0 + oo) << 9) + tid] = p;
    }
    __syncthreads();

    // ---- pre = attn @ v, i-range split across thread halves ----
    {
        const int half = tid >> 8;      // 0/1
        const int d = tid & 255;
        const float* vb = v + ((size_t)b << 17) + ((size_t)half << 16) + d;
        float ac0 = 0.f, ac1 = 0.f, ac2 = 0.f, ac3 = 0.f;
#pragma unroll 2
        for (int ii = 0; ii < 256; ii += 4) {
            const int i = (half << 8) + ii;
            float4 p0 = *(const float4*)&s_p[0][i];
            float4 p1 = *(const float4*)&s_p[1][i];
            float4 p2 = *(const float4*)&s_p[2][i];
            float4 p3 = *(const float4*)&s_p[3][i];
            float v0 = vb[(ii + 0) << 8];
            float v1 = vb[(ii + 1) << 8];
            float v2 = vb[(ii + 2) << 8];
            float v3 = vb[(ii + 3) << 8];
            ac0 = fmaf(p0.x, v0, ac0); ac1 = fmaf(p1.x, v0, ac1);
            ac2 = fmaf(p2.x, v0, ac2); ac3 = fmaf(p3.x, v0, ac3);
            ac0 = fmaf(p0.y, v1, ac0); ac1 = fmaf(p1.y, v1, ac1);
            ac2 = fmaf(p2.y, v1, ac2); ac3 = fmaf(p3.y, v1, ac3);
            ac0 = fmaf(p0.z, v2, ac0); ac1 = fmaf(p1.z, v2, ac1);
            ac2 = fmaf(p2.z, v2, ac2); ac3 = fmaf(p3.z, v2, ac3);
            ac0 = fmaf(p0.w, v3, ac0); ac1 = fmaf(p1.w, v3, ac1);
            ac2 = fmaf(p2.w, v3, ac2); ac3 = fmaf(p3.w, v3, ac3);
        }
        s_part[half][0][d] = ac0;
        s_part[half][1][d] = ac1;
        s_part[half][2][d] = ac2;
        s_part[half][3][d] = ac3;
    }
    __syncthreads();
    if (tid < 256) {
#pragma unroll
        for (int oo = 0; oo < OPB; oo++)
            s_pre[oo][tid] = s_part[0][oo][tid] + s_part[1][oo][tid];
    }
    __syncthreads();

    // ---- out = leaky(pre @ Wf^T + bf), 16 warps x 16 d-columns each ----
    const int hb = lane * 8;
    float pr0[8], pr1[8], pr2[8], pr3[8];
#pragma unroll
    for (int j = 0; j < 8; j++) {
        pr0[j] = s_pre[0][hb + j];
        pr1[j] = s_pre[1][hb + j];
        pr2[j] = s_pre[2][hb + j];
        pr3[j] = s_pre[3][hb + j];
    }

    float ov0 = 0.f, ov1 = 0.f, ov2 = 0.f, ov3 = 0.f;
    for (int c = 0; c < 16; c++) {
        const int d = (warp << 4) + c;
        const float4* wf = (const float4*)(Wf + ((size_t)d << 8) + hb);
        float4 f0 = wf[0], f1 = wf[1];
        float fr[8] = {f0.x, f0.y, f0.z, f0.w, f1.x, f1.y, f1.z, f1.w};
        float s0 = 0.f, s1 = 0.f, s2 = 0.f, s3 = 0.f;
#pragma unroll
        for (int j = 0; j < 8; j++) {
            s0 = fmaf(pr0[j], fr[j], s0);
            s1 = fmaf(pr1[j], fr[j], s1);
            s2 = fmaf(pr2[j], fr[j], s2);
            s3 = fmaf(pr3[j], fr[j], s3);
        }
#pragma unroll
        for (int off = 16; off > 0; off >>= 1) {
            s0 += __shfl_xor_sync(0xffffffffu, s0, off);
            s1 += __shfl_xor_sync(0xffffffffu, s1, off);
            s2 += __shfl_xor_sync(0xffffffffu, s2, off);
            s3 += __shfl_xor_sync(0xffffffffu, s3, off);
        }
        if (lane == c) { ov0 = s0; ov1 = s1; ov2 = s2; ov3 = s3; }
    }
    if (lane < 16) {
        const int d = (warp << 4) + lane;
        const float bfd = bf[d];
        float f0v = ov0 + bfd; f0v = (f0v >= 0.f) ? f0v : 0.01f * f0v;
        float f1v = ov1 + bfd; f1v = (f1v >= 0.f) ? f1v : 0.01f * f1v;
        float f2v = ov2 + bfd; f2v = (f2v >= 0.f) ? f2v : 0.01f * f2v;
        float f3v = ov3 + bfd; f3v = (f3v >= 0.f) ? f3v : 0.01f * f3v;
        out[((size_t)(b * O_ + o0 + 0) << 8) + d] = f0v;
        out[((size_t)(b * O_ + o0 + 1) << 8) + d] = f1v;
        out[((size_t)(b * O_ + o0 + 2) << 8) + d] = f2v;
        out[((size_t)(b * O_ + o0 + 3) << 8) + d] = f3v;
    }
}

// ---------------- launch ----------------
extern "C" void kernel_launch(void* const* d_in, const int* in_sizes, int n_in,
                              void* d_out, int out_size)
{
    const float* q  = (const float*)d_in[0];
    const float* k  = (const float*)d_in[1];
    const float* v  = (const float*)d_in[2];
    const int* mask = (const int*)d_in[3];
    const float* W1 = (const float*)d_in[4];
    const float* b1 = (const float*)d_in[5];
    const float* W2 = (const float*)d_in[6];
    // b2 (d_in[7]) cancels in softmax
    const float* Wf = (const float*)d_in[8];
    const float* bf = (const float*)d_in[9];

    float* out  = (float*)d_out;                  // (16,64,256)
    float* attn = out + (size_t)B_ * O_ * D_;     // (16,64,512)

    proj_kernel<<<288, 256>>>(q, k, W1, b1);
    score_kernel<<<1024, 128>>>(W2);
    finish_kernel<<<256, 512>>>(v, mask, Wf, bf, out, attn);
}

// round 11
// speedup vs baseline: 1.1970x; 1.0177x over previous
#include <cuda_runtime.h>
#include <cuda_fp16.h>
#include <cstdint>

#define B_ 16
#define O_ 64
#define I_ 512
#define D_ 256
#define OPB 4    // o-values per finish block
#define SOB 4    // o-values per score block

// ---------------- scratch (no allocation allowed) ----------------
__device__ float g_qp[B_ * O_ * D_];    // [b][o][h]  qp' = q@W1q^T + b1
__device__ float g_kpt[B_ * D_ * I_];   // [b][h][i]  kp^T
__device__ float g_sc[B_ * O_ * I_];    // [b][o][i]  raw scores

// ---------------- merged projection GEMM ----------------
// tile 128(m) x 64(h), Kc=32, 256 threads, 8x4 microtile, SINGLE buffer.
__global__ __launch_bounds__(256) void proj_kernel(
    const float* __restrict__ q, const float* __restrict__ k,
    const float* __restrict__ W1, const float* __restrict__ b1)
{
    __shared__ __align__(16) float Xs[32][132];  // [k][m], m=128 +4 pad
    __shared__ __align__(16) float Ws[32][68];   // [k][h], h=64 +4 pad

    const int bid = blockIdx.x;
    const bool isK = (bid >= 32);
    const int rb = isK ? bid - 32 : bid;
    const int m0 = (rb >> 2) * 128;
    const int h0 = (rb & 3) * 64;
    const float* __restrict__ X = isK ? k : q;
    const int colOff = isK ? 256 : 0;

    const int tid = threadIdx.x;
    const int tx = tid & 15;            // h dir: 16 x 4 = 64
    const int ty = tid >> 4;            // m dir: 16 x 8 = 128
    const int tx4 = tx * 4, ty8 = ty * 8;

    const int xr0 = tid >> 3;
    const int xc  = (tid & 7) << 2;
    const int wr0 = tid >> 3;           // 0..31
    const int wr1 = wr0 + 32;           // 32..63

    float acc[8][4];
#pragma unroll
    for (int r = 0; r < 8; r++)
#pragma unroll
        for (int c = 0; c < 4; c++) acc[r][c] = 0.f;

    for (int k0 = 0; k0 < 256; k0 += 32) {
#pragma unroll
        for (int l = 0; l < 4; l++) {
            const int r = xr0 + (l << 5);
            float4 xv = *(const float4*)(X + (size_t)(m0 + r) * 256 + k0 + xc);
            Xs[xc + 0][r] = xv.x; Xs[xc + 1][r] = xv.y;
            Xs[xc + 2][r] = xv.z; Xs[xc + 3][r] = xv.w;
        }
        {
            float4 wv0 = *(const float4*)(W1 + (size_t)(h0 + wr0) * 512 + colOff + k0 + xc);
            float4 wv1 = *(const float4*)(W1 + (size_t)(h0 + wr1) * 512 + colOff + k0 + xc);
            Ws[xc + 0][wr0] = wv0.x; Ws[xc + 1][wr0] = wv0.y;
            Ws[xc + 2][wr0] = wv0.z; Ws[xc + 3][wr0] = wv0.w;
            Ws[xc + 0][wr1] = wv1.x; Ws[xc + 1][wr1] = wv1.y;
            Ws[xc + 2][wr1] = wv1.z; Ws[xc + 3][wr1] = wv1.w;
        }
        __syncthreads();
#pragma unroll
        for (int kk = 0; kk < 32; kk++) {
            float4 a0 = *(const float4*)&Xs[kk][ty8];
            float4 a1 = *(const float4*)&Xs[kk][ty8 + 4];
            float4 bb = *(const float4*)&Ws[kk][tx4];
            float av[8] = {a0.x, a0.y, a0.z, a0.w, a1.x, a1.y, a1.z, a1.w};
            float bv[4] = {bb.x, bb.y, bb.z, bb.w};
#pragma unroll
            for (int r = 0; r < 8; r++)
#pragma unroll
                for (int c = 0; c < 4; c++)
                    acc[r][c] = fmaf(av[r], bv[c], acc[r][c]);
        }
        __syncthreads();
    }

    if (!isK) {
        const float b0 = b1[h0 + tx4 + 0];
        const float b1v = b1[h0 + tx4 + 1];
        const float b2v = b1[h0 + tx4 + 2];
        const float b3v = b1[h0 + tx4 + 3];
#pragma unroll
        for (int r = 0; r < 8; r++) {
            float4 ov;
            ov.x = acc[r][0] + b0;
            ov.y = acc[r][1] + b1v;
            ov.z = acc[r][2] + b2v;
            ov.w = acc[r][3] + b3v;
            *(float4*)(g_qp + (size_t)(m0 + ty8 + r) * 256 + h0 + tx4) = ov;
        }
    } else {
        const int b = m0 >> 9;               // tile never crosses batch
        const int i0 = (m0 & 511) + ty8;
#pragma unroll
        for (int c = 0; c < 4; c++) {
            const int h = h0 + tx4 + c;
            float* dst = g_kpt + ((size_t)(b * 256 + h) << 9) + i0;
            *(float4*)(dst)     = make_float4(acc[0][c], acc[1][c], acc[2][c], acc[3][c]);
            *(float4*)(dst + 4) = make_float4(acc[4][c], acc[5][c], acc[6][c], acc[7][c]);
        }
    }
}

// ---------------- packed f16x2 tanh (MUFU, 2 per op) ----------------
__device__ __forceinline__ __half2 h2tanh_mufu(__half2 x)
{
    unsigned xi = *reinterpret_cast<unsigned*>(&x);
    unsigned yi;
    asm("tanh.approx.f16x2 %0, %1;" : "=r"(yi) : "r"(xi));
    return *reinterpret_cast<__half2*>(&yi);
}

// ---------------- score kernel: grid 1024 = b(16) x o-group(16) x i-chunk(4) ----
// thread = one i; 4 o accumulators; h processed in f16x2 pairs, fp32 accumulate.
__global__ __launch_bounds__(128) void score_kernel(const float* __restrict__ W2)
{
    __shared__ __align__(16) __half2 s_qph[SOB][D_ / 2];   // qp packed pairs
    __shared__ __align__(16) float2 s_w2[D_ / 2];

    const int bx = blockIdx.x;
    const int b  = bx >> 6;
    const int og = (bx >> 2) & 15;
    const int ic = bx & 3;
    const int o0 = og << 2;
    const int tid = threadIdx.x;

    // stage qp (4x256 -> half2 pairs) and W2 (float2 pairs)
    {
        const float2* src = (const float2*)(g_qp + ((size_t)(b * O_ + o0) << 8));
#pragma unroll
        for (int l = 0; l < 4; l++) {
            const int idx = tid + (l << 7);          // 0..511
            const float2 v = src[idx];
            s_qph[idx >> 7][idx & 127] = __floats2half2_rn(v.x, v.y);
        }
        if (tid < 128) s_w2[tid] = ((const float2*)W2)[tid];
    }
    __syncthreads();

    const int i = (ic << 7) + tid;
    const float* kpt = g_kpt + ((size_t)b << 17) + i;

    float a0 = 0.f, a1 = 0.f, a2 = 0.f, a3 = 0.f;
#pragma unroll 4
    for (int hp = 0; hp < D_ / 2; hp++) {
        const float kv0 = kpt[(size_t)(2 * hp) << 9];
        const float kv1 = kpt[(size_t)(2 * hp + 1) << 9];
        const __half2 kvh = __floats2half2_rn(kv0, kv1);
        const float2 w = s_w2[hp];

        float2 t0 = __half22float2(h2tanh_mufu(__hadd2(s_qph[0][hp], kvh)));
        float2 t1 = __half22float2(h2tanh_mufu(__hadd2(s_qph[1][hp], kvh)));
        float2 t2 = __half22float2(h2tanh_mufu(__hadd2(s_qph[2][hp], kvh)));
        float2 t3 = __half22float2(h2tanh_mufu(__hadd2(s_qph[3][hp], kvh)));
        a0 = fmaf(t0.x, w.x, fmaf(t0.y, w.y, a0));
        a1 = fmaf(t1.x, w.x, fmaf(t1.y, w.y, a1));
        a2 = fmaf(t2.x, w.x, fmaf(t2.y, w.y, a2));
        a3 = fmaf(t3.x, w.x, fmaf(t3.y, w.y, a3));
    }
    float* dst = g_sc + ((size_t)(b * O_ + o0) << 9) + i;
    dst[0 << 9] = a0;
    dst[1 << 9] = a1;
    dst[2 << 9] = a2;
    dst[3 << 9] = a3;
}

// ---------------- finish kernel (R4-measured-best): grid 256, 512 threads ----
__global__ __launch_bounds__(512) void finish_kernel(
    const float* __restrict__ v, const int* __restrict__ mask,
    const float* __restrict__ Wf, const float* __restrict__ bf,
    float* __restrict__ out, float* __restrict__ attn_out)
{
    __shared__ __align__(16) float s_p[OPB][I_];        // 8KB
    __shared__ __align__(16) float s_part[2][OPB][D_];  // 8KB
    __shared__ __align__(16) float s_pre[OPB][D_];      // 4KB
    __shared__ float s_redA[OPB][16];
    __shared__ float s_redB[OPB][16];

    const int b  = blockIdx.x >> 4;
    const int o0 = (blockIdx.x & 15) << 2;
    const int tid = threadIdx.x;
    const int lane = tid & 31;
    const int warp = tid >> 5;      // 0..15

    // ---- softmax over i (tid = i) ----
    const int msk = mask[b * I_ + tid];
    const float* scp = g_sc + ((size_t)(b * O_ + o0) << 9) + tid;
    float sc[OPB], e[OPB];
#pragma unroll
    for (int oo = 0; oo < OPB; oo++) {
        sc[oo] = msk ? -1e30f : scp[(size_t)oo << 9];
        float m = sc[oo];
#pragma unroll
        for (int off = 16; off > 0; off >>= 1)
            m = fmaxf(m, __shfl_xor_sync(0xffffffffu, m, off));
        if (lane == 0) s_redA[oo][warp] = m;
    }
    __syncthreads();
#pragma unroll
    for (int oo = 0; oo < OPB; oo++) {
        float mx = s_redA[oo][0];
#pragma unroll
        for (int j = 1; j < 16; j++) mx = fmaxf(mx, s_redA[oo][j]);
        e[oo] = __expf(sc[oo] - mx);
        float ssum = e[oo];
#pragma unroll
        for (int off = 16; off > 0; off >>= 1)
            ssum += __shfl_xor_sync(0xffffffffu, ssum, off);
        if (lane == 0) s_redB[oo][warp] = ssum;
    }
    __syncthreads();
#pragma unroll
    for (int oo = 0; oo < OPB; oo++) {
        float tot = 0.f;
#pragma unroll
        for (int j = 0; j < 16; j++) tot += s_redB[oo][j];
        const float p = e[oo] * __fdividef(1.0f, tot);
        s_p[oo][tid] = p;
        attn_out[((size_t)(b * O_ + o0 + oo) << 9) + tid] = p;
    }
    __syncthreads();

    // ---- pre = attn @ v, i-range split across thread halves ----
    {
        const int half = tid >> 8;      // 0/1
        const int d = tid & 255;
        const float* vb = v + ((size_t)b << 17) + ((size_t)half << 16) + d;
        float ac0 = 0.f, ac1 = 0.f, ac2 = 0.f, ac3 = 0.f;
#pragma unroll 2
        for (int ii = 0; ii < 256; ii += 4) {
            const int i = (half << 8) + ii;
            float4 p0 = *(const float4*)&s_p[0][i];
            float4 p1 = *(const float4*)&s_p[1][i];
            float4 p2 = *(const float4*)&s_p[2][i];
            float4 p3 = *(const float4*)&s_p[3][i];
            float v0 = vb[(ii + 0) << 8];
            float v1 = vb[(ii + 1) << 8];
            float v2 = vb[(ii + 2) << 8];
            float v3 = vb[(ii + 3) << 8];
            ac0 = fmaf(p0.x, v0, ac0); ac1 = fmaf(p1.x, v0, ac1);
            ac2 = fmaf(p2.x, v0, ac2); ac3 = fmaf(p3.x, v0, ac3);
            ac0 = fmaf(p0.y, v1, ac0); ac1 = fmaf(p1.y, v1, ac1);
            ac2 = fmaf(p2.y, v1, ac2); ac3 = fmaf(p3.y, v1, ac3);
            ac0 = fmaf(p0.z, v2, ac0); ac1 = fmaf(p1.z, v2, ac1);
            ac2 = fmaf(p2.z, v2, ac2); ac3 = fmaf(p3.z, v2, ac3);
            ac0 = fmaf(p0.w, v3, ac0); ac1 = fmaf(p1.w, v3, ac1);
            ac2 = fmaf(p2.w, v3, ac2); ac3 = fmaf(p3.w, v3, ac3);
        }
        s_part[half][0][d] = ac0;
        s_part[half][1][d] = ac1;
        s_part[half][2][d] = ac2;
        s_part[half][3][d] = ac3;
    }
    __syncthreads();
    if (tid < 256) {
#pragma unroll
        for (int oo = 0; oo < OPB; oo++)
            s_pre[oo][tid] = s_part[0][oo][tid] + s_part[1][oo][tid];
    }
    __syncthreads();

    // ---- out = leaky(pre @ Wf^T + bf), 16 warps x 16 d-columns each ----
    const int hb = lane * 8;
    float pr0[8], pr1[8], pr2[8], pr3[8];
#pragma unroll
    for (int j = 0; j < 8; j++) {
        pr0[j] = s_pre[0][hb + j];
        pr1[j] = s_pre[1][hb + j];
        pr2[j] = s_pre[2][hb + j];
        pr3[j] = s_pre[3][hb + j];
    }

    float ov0 = 0.f, ov1 = 0.f, ov2 = 0.f, ov3 = 0.f;
    for (int c = 0; c < 16; c++) {
        const int d = (warp << 4) + c;
        const float4* wf = (const float4*)(Wf + ((size_t)d << 8) + hb);
        float4 f0 = wf[0], f1 = wf[1];
        float fr[8] = {f0.x, f0.y, f0.z, f0.w, f1.x, f1.y, f1.z, f1.w};
        float s0 = 0.f, s1 = 0.f, s2 = 0.f, s3 = 0.f;
#pragma unroll
        for (int j = 0; j < 8; j++) {
            s0 = fmaf(pr0[j], fr[j], s0);
            s1 = fmaf(pr1[j], fr[j], s1);
            s2 = fmaf(pr2[j], fr[j], s2);
            s3 = fmaf(pr3[j], fr[j], s3);
        }
#pragma unroll
        for (int off = 16; off > 0; off >>= 1) {
            s0 += __shfl_xor_sync(0xffffffffu, s0, off);
            s1 += __shfl_xor_sync(0xffffffffu, s1, off);
            s2 += __shfl_xor_sync(0xffffffffu, s2, off);
            s3 += __shfl_xor_sync(0xffffffffu, s3, off);
        }
        if (lane == c) { ov0 = s0; ov1 = s1; ov2 = s2; ov3 = s3; }
    }
    if (lane < 16) {
        const int d = (warp << 4) + lane;
        const float bfd = bf[d];
        float f0v = ov0 + bfd; f0v = (f0v >= 0.f) ? f0v : 0.01f * f0v;
        float f1v = ov1 + bfd; f1v = (f1v >= 0.f) ? f1v : 0.01f * f1v;
        float f2v = ov2 + bfd; f2v = (f2v >= 0.f) ? f2v : 0.01f * f2v;
        float f3v = ov3 + bfd; f3v = (f3v >= 0.f) ? f3v : 0.01f * f3v;
        out[((size_t)(b * O_ + o0 + 0) << 8) + d] = f0v;
        out[((size_t)(b * O_ + o0 + 1) << 8) + d] = f1v;
        out[((size_t)(b * O_ + o0 + 2) << 8) + d] = f2v;
        out[((size_t)(b * O_ + o0 + 3) << 8) + d] = f3v;
    }
}

// ---------------- launch ----------------
extern "C" void kernel_launch(void* const* d_in, const int* in_sizes, int n_in,
                              void* d_out, int out_size)
{
    const float* q  = (const float*)d_in[0];
    const float* k  = (const float*)d_in[1];
    const float* v  = (const float*)d_in[2];
    const int* mask = (const int*)d_in[3];
    const float* W1 = (const float*)d_in[4];
    const float* b1 = (const float*)d_in[5];
    const float* W2 = (const float*)d_in[6];
    // b2 (d_in[7]) cancels in softmax
    const float* Wf = (const float*)d_in[8];
    const float* bf = (const float*)d_in[9];

    float* out  = (float*)d_out;                  // (16,64,256)
    float* attn = out + (size_t)B_ * O_ * D_;     // (16,64,512)

    proj_kernel<<<288, 256>>>(q, k, W1, b1);
    score_kernel<<<1024, 128>>>(W2);
    finish_kernel<<<256, 512>>>(v, mask, Wf, bf, out, attn);
}

// round 13
// speedup vs baseline: 1.3043x; 1.0897x over previous
#include <cuda_runtime.h>
#include <cuda_fp16.h>
#include <cstdint>

#define B_ 16
#define O_ 64
#define I_ 512
#define D_ 256
#define OPB 4    // o-values per fused block

// ---------------- scratch (no allocation allowed) ----------------
__device__ float g_qp[B_ * O_ * D_];    // [b][o][h]  qp' = q@W1q^T + b1
__device__ float g_kpt[B_ * D_ * I_];   // [b][h][i]  kp^T

// ---------------- merged projection GEMM ----------------
// tile 128(m) x 64(h), Kc=32, 256 threads, 8x4 microtile, SINGLE buffer.
__global__ __launch_bounds__(256) void proj_kernel(
    const float* __restrict__ q, const float* __restrict__ k,
    const float* __restrict__ W1, const float* __restrict__ b1)
{
    __shared__ __align__(16) float Xs[32][132];  // [k][m], m=128 +4 pad
    __shared__ __align__(16) float Ws[32][68];   // [k][h], h=64 +4 pad

    const int bid = blockIdx.x;
    const bool isK = (bid >= 32);
    const int rb = isK ? bid - 32 : bid;
    const int m0 = (rb >> 2) * 128;
    const int h0 = (rb & 3) * 64;
    const float* __restrict__ X = isK ? k : q;
    const int colOff = isK ? 256 : 0;

    const int tid = threadIdx.x;
    const int tx = tid & 15;            // h dir: 16 x 4 = 64
    const int ty = tid >> 4;            // m dir: 16 x 8 = 128
    const int tx4 = tx * 4, ty8 = ty * 8;

    const int xr0 = tid >> 3;
    const int xc  = (tid & 7) << 2;
    const int wr0 = tid >> 3;           // 0..31
    const int wr1 = wr0 + 32;           // 32..63

    float acc[8][4];
#pragma unroll
    for (int r = 0; r < 8; r++)
#pragma unroll
        for (int c = 0; c < 4; c++) acc[r][c] = 0.f;

    for (int k0 = 0; k0 < 256; k0 += 32) {
#pragma unroll
        for (int l = 0; l < 4; l++) {
            const int r = xr0 + (l << 5);
            float4 xv = *(const float4*)(X + (size_t)(m0 + r) * 256 + k0 + xc);
            Xs[xc + 0][r] = xv.x; Xs[xc + 1][r] = xv.y;
            Xs[xc + 2][r] = xv.z; Xs[xc + 3][r] = xv.w;
        }
        {
            float4 wv0 = *(const float4*)(W1 + (size_t)(h0 + wr0) * 512 + colOff + k0 + xc);
            float4 wv1 = *(const float4*)(W1 + (size_t)(h0 + wr1) * 512 + colOff + k0 + xc);
            Ws[xc + 0][wr0] = wv0.x; Ws[xc + 1][wr0] = wv0.y;
            Ws[xc + 2][wr0] = wv0.z; Ws[xc + 3][wr0] = wv0.w;
            Ws[xc + 0][wr1] = wv1.x; Ws[xc + 1][wr1] = wv1.y;
            Ws[xc + 2][wr1] = wv1.z; Ws[xc + 3][wr1] = wv1.w;
        }
        __syncthreads();
#pragma unroll
        for (int kk = 0; kk < 32; kk++) {
            float4 a0 = *(const float4*)&Xs[kk][ty8];
            float4 a1 = *(const float4*)&Xs[kk][ty8 + 4];
            float4 bb = *(const float4*)&Ws[kk][tx4];
            float av[8] = {a0.x, a0.y, a0.z, a0.w, a1.x, a1.y, a1.z, a1.w};
            float bv[4] = {bb.x, bb.y, bb.z, bb.w};
#pragma unroll
            for (int r = 0; r < 8; r++)
#pragma unroll
                for (int c = 0; c < 4; c++)
                    acc[r][c] = fmaf(av[r], bv[c], acc[r][c]);
        }
        __syncthreads();
    }

    if (!isK) {
        const float b0 = b1[h0 + tx4 + 0];
        const float b1v = b1[h0 + tx4 + 1];
        const float b2v = b1[h0 + tx4 + 2];
        const float b3v = b1[h0 + tx4 + 3];
#pragma unroll
        for (int r = 0; r < 8; r++) {
            float4 ov;
            ov.x = acc[r][0] + b0;
            ov.y = acc[r][1] + b1v;
            ov.z = acc[r][2] + b2v;
            ov.w = acc[r][3] + b3v;
            *(float4*)(g_qp + (size_t)(m0 + ty8 + r) * 256 + h0 + tx4) = ov;
        }
    } else {
        const int b = m0 >> 9;               // tile never crosses batch
        const int i0 = (m0 & 511) + ty8;
#pragma unroll
        for (int c = 0; c < 4; c++) {
            const int h = h0 + tx4 + c;
            float* dst = g_kpt + ((size_t)(b * 256 + h) << 9) + i0;
            *(float4*)(dst)     = make_float4(acc[0][c], acc[1][c], acc[2][c], acc[3][c]);
            *(float4*)(dst + 4) = make_float4(acc[4][c], acc[5][c], acc[6][c], acc[7][c]);
        }
    }
}

// ---------------- packed f16x2 tanh (MUFU, 2 per op) ----------------
__device__ __forceinline__ __half2 h2tanh_mufu(__half2 x)
{
    unsigned xi = *reinterpret_cast<unsigned*>(&x);
    unsigned yi;
    asm("tanh.approx.f16x2 %0, %1;" : "=r"(yi) : "r"(xi));
    return *reinterpret_cast<__half2*>(&yi);
}

// ---------------- fused score+softmax+attn@v+Wf kernel ----------------
// grid 256 = b(16) x o-group(16); 512 threads; score phase: thread = i.
__global__ __launch_bounds__(512) void fused_kernel(
    const float* __restrict__ v, const int* __restrict__ mask,
    const float* __restrict__ W2, const float* __restrict__ Wf,
    const float* __restrict__ bf,
    float* __restrict__ out, float* __restrict__ attn_out)
{
    __shared__ __align__(16) __half2 s_qph[OPB][D_ / 2];  // 2KB
    __shared__ __align__(16) float2 s_w2[D_ / 2];         // 1KB
    __shared__ __align__(16) float s_p[OPB][I_];          // 8KB
    __shared__ __align__(16) float s_part[2][OPB][D_];    // 8KB
    __shared__ __align__(16) float s_pre[OPB][D_];        // 4KB
    __shared__ float s_redA[OPB][16];
    __shared__ float s_redB[OPB][16];

    const int b  = blockIdx.x >> 4;
    const int o0 = (blockIdx.x & 15) << 2;
    const int tid = threadIdx.x;
    const int lane = tid & 31;
    const int warp = tid >> 5;      // 0..15

    // ---- stage qp (4x256 -> half2 pairs) and W2 ----
    {
        const float2* src = (const float2*)(g_qp + ((size_t)(b * O_ + o0) << 8));
        const float2 vv = src[tid];                    // 512 float2 = 4x256 floats
        s_qph[tid >> 7][tid & 127] = __floats2half2_rn(vv.x, vv.y);
        if (tid < 128) s_w2[tid] = ((const float2*)W2)[tid];
    }
    __syncthreads();

    // ---- score phase: thread = i (512 i's) ----
    const float* kpt = g_kpt + ((size_t)b << 17) + tid;
    float a0 = 0.f, a1 = 0.f, a2 = 0.f, a3 = 0.f;
#pragma unroll 4
    for (int hp = 0; hp < D_ / 2; hp++) {
        const float kv0 = kpt[(size_t)(2 * hp) << 9];
        const float kv1 = kpt[(size_t)(2 * hp + 1) << 9];
        const __half2 kvh = __floats2half2_rn(kv0, kv1);
        const float2 w = s_w2[hp];

        float2 t0 = __half22float2(h2tanh_mufu(__hadd2(s_qph[0][hp], kvh)));
        float2 t1 = __half22float2(h2tanh_mufu(__hadd2(s_qph[1][hp], kvh)));
        float2 t2 = __half22float2(h2tanh_mufu(__hadd2(s_qph[2][hp], kvh)));
        float2 t3 = __half22float2(h2tanh_mufu(__hadd2(s_qph[3][hp], kvh)));
        a0 = fmaf(t0.x, w.x, fmaf(t0.y, w.y, a0));
        a1 = fmaf(t1.x, w.x, fmaf(t1.y, w.y, a1));
        a2 = fmaf(t2.x, w.x, fmaf(t2.y, w.y, a2));
        a3 = fmaf(t3.x, w.x, fmaf(t3.y, w.y, a3));
    }

    // ---- softmax over i (scores live in registers) ----
    const int msk = mask[b * I_ + tid];
    float sc[OPB], e[OPB];
    sc[0] = msk ? -1e30f : a0;
    sc[1] = msk ? -1e30f : a1;
    sc[2] = msk ? -1e30f : a2;
    sc[3] = msk ? -1e30f : a3;
#pragma unroll
    for (int oo = 0; oo < OPB; oo++) {
        float m = sc[oo];
#pragma unroll
        for (int off = 16; off > 0; off >>= 1)
            m = fmaxf(m, __shfl_xor_sync(0xffffffffu, m, off));
        if (lane == 0) s_redA[oo][warp] = m;
    }
    __syncthreads();
#pragma unroll
    for (int oo = 0; oo < OPB; oo++) {
        float mx = s_redA[oo][0];
#pragma unroll
        for (int j = 1; j < 16; j++) mx = fmaxf(mx, s_redA[oo][j]);
        e[oo] = __expf(sc[oo] - mx);
        float ssum = e[oo];
#pragma unroll
        for (int off = 16; off > 0; off >>= 1)
            ssum += __shfl_xor_sync(0xffffffffu, ssum, off);
        if (lane == 0) s_redB[oo][warp] = ssum;
    }
    __syncthreads();
#pragma unroll
    for (int oo = 0; oo < OPB; oo++) {
        float tot = 0.f;
#pragma unroll
        for (int j = 0; j < 16; j++) tot += s_redB[oo][j];
        const float p = e[oo] * __fdividef(1.0f, tot);
        s_p[oo][tid] = p;
        attn_out[((size_t)(b * O_ + o0 + oo) << 9) + tid] = p;
    }
    __syncthreads();

    // ---- pre = attn @ v, i-range split across thread halves ----
    {
        const int half = tid >> 8;      // 0/1
        const int d = tid & 255;
        const float* vb = v + ((size_t)b << 17) + ((size_t)half << 16) + d;
        float ac0 = 0.f, ac1 = 0.f, ac2 = 0.f, ac3 = 0.f;
#pragma unroll 2
        for (int ii = 0; ii < 256; ii += 4) {
            const int i = (half << 8) + ii;
            float4 p0 = *(const float4*)&s_p[0][i];
            float4 p1 = *(const float4*)&s_p[1][i];
            float4 p2 = *(const float4*)&s_p[2][i];
            float4 p3 = *(const float4*)&s_p[3][i];
            float v0 = vb[(ii + 0) << 8];
            float v1 = vb[(ii + 1) << 8];
            float v2 = vb[(ii + 2) << 8];
            float v3 = vb[(ii + 3) << 8];
            ac0 = fmaf(p0.x, v0, ac0); ac1 = fmaf(p1.x, v0, ac1);
            ac2 = fmaf(p2.x, v0, ac2); ac3 = fmaf(p3.x, v0, ac3);
            ac0 = fmaf(p0.y, v1, ac0); ac1 = fmaf(p1.y, v1, ac1);
            ac2 = fmaf(p2.y, v1, ac2); ac3 = fmaf(p3.y, v1, ac3);
            ac0 = fmaf(p0.z, v2, ac0); ac1 = fmaf(p1.z, v2, ac1);
            ac2 = fmaf(p2.z, v2, ac2); ac3 = fmaf(p3.z, v2, ac3);
            ac0 = fmaf(p0.w, v3, ac0); ac1 = fmaf(p1.w, v3, ac1);
            ac2 = fmaf(p2.w, v3, ac2); ac3 = fmaf(p3.w, v3, ac3);
        }
        s_part[half][0][d] = ac0;
        s_part[half][1][d] = ac1;
        s_part[half][2][d] = ac2;
        s_part[half][3][d] = ac3;
    }
    __syncthreads();
    if (tid < 256) {
#pragma unroll
        for (int oo = 0; oo < OPB; oo++)
            s_pre[oo][tid] = s_part[0][oo][tid] + s_part[1][oo][tid];
    }
    __syncthreads();

    // ---- out = leaky(pre @ Wf^T + bf), 16 warps x 16 d-columns each ----
    const int hb = lane * 8;
    float pr0[8], pr1[8], pr2[8], pr3[8];
#pragma unroll
    for (int j = 0; j < 8; j++) {
        pr0[j] = s_pre[0][hb + j];
        pr1[j] = s_pre[1][hb + j];
        pr2[j] = s_pre[2][hb + j];
        pr3[j] = s_pre[3][hb + j];
    }

    float ov0 = 0.f, ov1 = 0.f, ov2 = 0.f, ov3 = 0.f;
    for (int c = 0; c < 16; c++) {
        const int d = (warp << 4) + c;
        const float4* wf = (const float4*)(Wf + ((size_t)d << 8) + hb);
        float4 f0 = wf[0], f1 = wf[1];
        float fr[8] = {f0.x, f0.y, f0.z, f0.w, f1.x, f1.y, f1.z, f1.w};
        float s0 = 0.f, s1 = 0.f, s2 = 0.f, s3 = 0.f;
#pragma unroll
        for (int j = 0; j < 8; j++) {
            s0 = fmaf(pr0[j], fr[j], s0);
            s1 = fmaf(pr1[j], fr[j], s1);
            s2 = fmaf(pr2[j], fr[j], s2);
            s3 = fmaf(pr3[j], fr[j], s3);
        }
#pragma unroll
        for (int off = 16; off > 0; off >>= 1) {
            s0 += __shfl_xor_sync(0xffffffffu, s0, off);
            s1 += __shfl_xor_sync(0xffffffffu, s1, off);
            s2 += __shfl_xor_sync(0xffffffffu, s2, off);
            s3 += __shfl_xor_sync(0xffffffffu, s3, off);
        }
        if (lane == c) { ov0 = s0; ov1 = s1; ov2 = s2; ov3 = s3; }
    }
    if (lane < 16) {
        const int d = (warp << 4) + lane;
        const float bfd = bf[d];
        float f0v = ov0 + bfd; f0v = (f0v >= 0.f) ? f0v : 0.01f * f0v;
        float f1v = ov1 + bfd; f1v = (f1v >= 0.f) ? f1v : 0.01f * f1v;
        float f2v = ov2 + bfd; f2v = (f2v >= 0.f) ? f2v : 0.01f * f2v;
        float f3v = ov3 + bfd; f3v = (f3v >= 0.f) ? f3v : 0.01f * f3v;
        out[((size_t)(b * O_ + o0 + 0) << 8) + d] = f0v;
        out[((size_t)(b * O_ + o0 + 1) << 8) + d] = f1v;
        out[((size_t)(b * O_ + o0 + 2) << 8) + d] = f2v;
        out[((size_t)(b * O_ + o0 + 3) << 8) + d] = f3v;
    }
}

// ---------------- launch ----------------
extern "C" void kernel_launch(void* const* d_in, const int* in_sizes, int n_in,
                              void* d_out, int out_size)
{
    const float* q  = (const float*)d_in[0];
    const float* k  = (const float*)d_in[1];
    const float* v  = (const float*)d_in[2];
    const int* mask = (const int*)d_in[3];
    const float* W1 = (const float*)d_in[4];
    const float* b1 = (const float*)d_in[5];
    const float* W2 = (const float*)d_in[6];
    // b2 (d_in[7]) cancels in softmax
    const float* Wf = (const float*)d_in[8];
    const float* bf = (const float*)d_in[9];

    float* out  = (float*)d_out;                  // (16,64,256)
    float* attn = out + (size_t)B_ * O_ * D_;     // (16,64,512)

    proj_kernel<<<288, 256>>>(q, k, W1, b1);
    fused_kernel<<<256, 512>>>(v, mask, W2, Wf, bf, out, attn);
}

// round 15
// speedup vs baseline: 1.3703x; 1.0506x over previous
#include <cuda_runtime.h>
#include <cuda_fp16.h>
#include <cstdint>

#define B_ 16
#define O_ 64
#define I_ 512
#define D_ 256
#define OPB 4    // o-values per fused block

// ---------------- scratch (no allocation allowed) ----------------
__device__ float   g_qp[B_ * O_ * D_];          // [b][o][h]  qp' = q@W1q^T + b1
__device__ __half2 g_kpth[B_ * (D_ / 2) * I_];  // [b][hp][i] kp^T as half2 pairs (4MB)

// ---------------- merged projection GEMM ----------------
// tile 128(m) x 64(h), Kc=32, 256 threads, 8x4 microtile, SINGLE buffer.
__global__ __launch_bounds__(256) void proj_kernel(
    const float* __restrict__ q, const float* __restrict__ k,
    const float* __restrict__ W1, const float* __restrict__ b1)
{
    __shared__ __align__(16) float Xs[32][132];  // [k][m], m=128 +4 pad
    __shared__ __align__(16) float Ws[32][68];   // [k][h], h=64 +4 pad

    const int bid = blockIdx.x;
    const bool isK = (bid >= 32);
    const int rb = isK ? bid - 32 : bid;
    const int m0 = (rb >> 2) * 128;
    const int h0 = (rb & 3) * 64;
    const float* __restrict__ X = isK ? k : q;
    const int colOff = isK ? 256 : 0;

    const int tid = threadIdx.x;
    const int tx = tid & 15;            // h dir: 16 x 4 = 64
    const int ty = tid >> 4;            // m dir: 16 x 8 = 128
    const int tx4 = tx * 4, ty8 = ty * 8;

    const int xr0 = tid >> 3;
    const int xc  = (tid & 7) << 2;
    const int wr0 = tid >> 3;           // 0..31
    const int wr1 = wr0 + 32;           // 32..63

    float acc[8][4];
#pragma unroll
    for (int r = 0; r < 8; r++)
#pragma unroll
        for (int c = 0; c < 4; c++) acc[r][c] = 0.f;

    for (int k0 = 0; k0 < 256; k0 += 32) {
#pragma unroll
        for (int l = 0; l < 4; l++) {
            const int r = xr0 + (l << 5);
            float4 xv = *(const float4*)(X + (size_t)(m0 + r) * 256 + k0 + xc);
            Xs[xc + 0][r] = xv.x; Xs[xc + 1][r] = xv.y;
            Xs[xc + 2][r] = xv.z; Xs[xc + 3][r] = xv.w;
        }
        {
            float4 wv0 = *(const float4*)(W1 + (size_t)(h0 + wr0) * 512 + colOff + k0 + xc);
            float4 wv1 = *(const float4*)(W1 + (size_t)(h0 + wr1) * 512 + colOff + k0 + xc);
            Ws[xc + 0][wr0] = wv0.x; Ws[xc + 1][wr0] = wv0.y;
            Ws[xc + 2][wr0] = wv0.z; Ws[xc + 3][wr0] = wv0.w;
            Ws[xc + 0][wr1] = wv1.x; Ws[xc + 1][wr1] = wv1.y;
            Ws[xc + 2][wr1] = wv1.z; Ws[xc + 3][wr1] = wv1.w;
        }
        __syncthreads();
#pragma unroll
        for (int kk = 0; kk < 32; kk++) {
            float4 a0 = *(const float4*)&Xs[kk][ty8];
            float4 a1 = *(const float4*)&Xs[kk][ty8 + 4];
            float4 bb = *(const float4*)&Ws[kk][tx4];
            float av[8] = {a0.x, a0.y, a0.z, a0.w, a1.x, a1.y, a1.z, a1.w};
            float bv[4] = {bb.x, bb.y, bb.z, bb.w};
#pragma unroll
            for (int r = 0; r < 8; r++)
#pragma unroll
                for (int c = 0; c < 4; c++)
                    acc[r][c] = fmaf(av[r], bv[c], acc[r][c]);
        }
        __syncthreads();
    }

    if (!isK) {
        const float b0 = b1[h0 + tx4 + 0];
        const float b1v = b1[h0 + tx4 + 1];
        const float b2v = b1[h0 + tx4 + 2];
        const float b3v = b1[h0 + tx4 + 3];
#pragma unroll
        for (int r = 0; r < 8; r++) {
            float4 ov;
            ov.x = acc[r][0] + b0;
            ov.y = acc[r][1] + b1v;
            ov.z = acc[r][2] + b2v;
            ov.w = acc[r][3] + b3v;
            *(float4*)(g_qp + (size_t)(m0 + ty8 + r) * 256 + h0 + tx4) = ov;
        }
    } else {
        // kp: store as half2 pair layout [b][hp][i]
        const int b = m0 >> 9;               // tile never crosses batch
        const int i0 = (m0 & 511) + ty8;     // multiple of 8
#pragma unroll
        for (int j = 0; j < 2; j++) {        // two h-pairs per thread
            const int hp = ((h0 + tx4) >> 1) + j;
            __half2 hv[8];
#pragma unroll
            for (int r = 0; r < 8; r++)
                hv[r] = __floats2half2_rn(acc[r][2 * j], acc[r][2 * j + 1]);
            __half2* dst = g_kpth + ((size_t)(b * 128 + hp) << 9) + i0;
            *(uint4*)(dst)     = *(uint4*)&hv[0];   // 4 half2 = 16B
            *(uint4*)(dst + 4) = *(uint4*)&hv[4];
        }
    }
}

// ---------------- packed f16x2 tanh (MUFU, 2 per op) ----------------
__device__ __forceinline__ __half2 h2tanh_mufu(__half2 x)
{
    unsigned xi = *reinterpret_cast<unsigned*>(&x);
    unsigned yi;
    asm("tanh.approx.f16x2 %0, %1;" : "=r"(yi) : "r"(xi));
    return *reinterpret_cast<__half2*>(&yi);
}

// ---------------- fused score+softmax+attn@v+Wf kernel ----------------
// grid 256 = b(16) x o-group(16); 512 threads; score phase: thread = i.
__global__ __launch_bounds__(512) void fused_kernel(
    const float* __restrict__ v, const int* __restrict__ mask,
    const float* __restrict__ W2, const float* __restrict__ Wf,
    const float* __restrict__ bf,
    float* __restrict__ out, float* __restrict__ attn_out)
{
    __shared__ __align__(16) __half2 s_qph[OPB][D_ / 2];  // 2KB
    __shared__ __align__(16) float2 s_w2[D_ / 2];         // 1KB
    __shared__ __align__(16) float s_p[OPB][I_];          // 8KB
    __shared__ __align__(16) float s_part[2][OPB][D_];    // 8KB
    __shared__ __align__(16) float s_pre[OPB][D_];        // 4KB
    __shared__ float s_redA[OPB][16];
    __shared__ float s_redB[OPB][16];

    const int b  = blockIdx.x >> 4;
    const int o0 = (blockIdx.x & 15) << 2;
    const int tid = threadIdx.x;
    const int lane = tid & 31;
    const int warp = tid >> 5;      // 0..15

    // ---- stage qp (4x256 -> half2 pairs) and W2 ----
    {
        const float2* src = (const float2*)(g_qp + ((size_t)(b * O_ + o0) << 8));
        const float2 vv = src[tid];                    // 512 float2 = 4x256 floats
        s_qph[tid >> 7][tid & 127] = __floats2half2_rn(vv.x, vv.y);
        if (tid < 128) s_w2[tid] = ((const float2*)W2)[tid];
    }
    __syncthreads();

    // ---- score phase: thread = i (512 i's); kpt already half2 pairs ----
    const __half2* kpt = g_kpth + ((size_t)b << 16) + tid;
    float a0 = 0.f, a1 = 0.f, a2 = 0.f, a3 = 0.f;
#pragma unroll 8
    for (int hp = 0; hp < D_ / 2; hp++) {
        const __half2 kvh = kpt[(size_t)hp << 9];
        const float2 w = s_w2[hp];

        float2 t0 = __half22float2(h2tanh_mufu(__hadd2(s_qph[0][hp], kvh)));
        float2 t1 = __half22float2(h2tanh_mufu(__hadd2(s_qph[1][hp], kvh)));
        float2 t2 = __half22float2(h2tanh_mufu(__hadd2(s_qph[2][hp], kvh)));
        float2 t3 = __half22float2(h2tanh_mufu(__hadd2(s_qph[3][hp], kvh)));
        a0 = fmaf(t0.x, w.x, fmaf(t0.y, w.y, a0));
        a1 = fmaf(t1.x, w.x, fmaf(t1.y, w.y, a1));
        a2 = fmaf(t2.x, w.x, fmaf(t2.y, w.y, a2));
        a3 = fmaf(t3.x, w.x, fmaf(t3.y, w.y, a3));
    }

    // ---- softmax over i (scores live in registers) ----
    const int msk = mask[b * I_ + tid];
    float sc[OPB], e[OPB];
    sc[0] = msk ? -1e30f : a0;
    sc[1] = msk ? -1e30f : a1;
    sc[2] = msk ? -1e30f : a2;
    sc[3] = msk ? -1e30f : a3;
#pragma unroll
    for (int oo = 0; oo < OPB; oo++) {
        float m = sc[oo];
#pragma unroll
        for (int off = 16; off > 0; off >>= 1)
            m = fmaxf(m, __shfl_xor_sync(0xffffffffu, m, off));
        if (lane == 0) s_redA[oo][warp] = m;
    }
    __syncthreads();
#pragma unroll
    for (int oo = 0; oo < OPB; oo++) {
        float mx = s_redA[oo][0];
#pragma unroll
        for (int j = 1; j < 16; j++) mx = fmaxf(mx, s_redA[oo][j]);
        e[oo] = __expf(sc[oo] - mx);
        float ssum = e[oo];
#pragma unroll
        for (int off = 16; off > 0; off >>= 1)
            ssum += __shfl_xor_sync(0xffffffffu, ssum, off);
        if (lane == 0) s_redB[oo][warp] = ssum;
    }
    __syncthreads();
#pragma unroll
    for (int oo = 0; oo < OPB; oo++) {
        float tot = 0.f;
#pragma unroll
        for (int j = 0; j < 16; j++) tot += s_redB[oo][j];
        const float p = e[oo] * __fdividef(1.0f, tot);
        s_p[oo][tid] = p;
        attn_out[((size_t)(b * O_ + o0 + oo) << 9) + tid] = p;
    }
    __syncthreads();

    // ---- pre = attn @ v, i-range split across thread halves ----
    {
        const int half = tid >> 8;      // 0/1
        const int d = tid & 255;
        const float* vb = v + ((size_t)b << 17) + ((size_t)half << 16) + d;
        float ac0 = 0.f, ac1 = 0.f, ac2 = 0.f, ac3 = 0.f;
#pragma unroll 2
        for (int ii = 0; ii < 256; ii += 4) {
            const int i = (half << 8) + ii;
            float4 p0 = *(const float4*)&s_p[0][i];
            float4 p1 = *(const float4*)&s_p[1][i];
            float4 p2 = *(const float4*)&s_p[2][i];
            float4 p3 = *(const float4*)&s_p[3][i];
            float v0 = vb[(ii + 0) << 8];
            float v1 = vb[(ii + 1) << 8];
            float v2 = vb[(ii + 2) << 8];
            float v3 = vb[(ii + 3) << 8];
            ac0 = fmaf(p0.x, v0, ac0); ac1 = fmaf(p1.x, v0, ac1);
            ac2 = fmaf(p2.x, v0, ac2); ac3 = fmaf(p3.x, v0, ac3);
            ac0 = fmaf(p0.y, v1, ac0); ac1 = fmaf(p1.y, v1, ac1);
            ac2 = fmaf(p2.y, v1, ac2); ac3 = fmaf(p3.y, v1, ac3);
            ac0 = fmaf(p0.z, v2, ac0); ac1 = fmaf(p1.z, v2, ac1);
            ac2 = fmaf(p2.z, v2, ac2); ac3 = fmaf(p3.z, v2, ac3);
            ac0 = fmaf(p0.w, v3, ac0); ac1 = fmaf(p1.w, v3, ac1);
            ac2 = fmaf(p2.w, v3, ac2); ac3 = fmaf(p3.w, v3, ac3);
        }
        s_part[half][0][d] = ac0;
        s_part[half][1][d] = ac1;
        s_part[half][2][d] = ac2;
        s_part[half][3][d] = ac3;
    }
    __syncthreads();
    if (tid < 256) {
#pragma unroll
        for (int oo = 0; oo < OPB; oo++)
            s_pre[oo][tid] = s_part[0][oo][tid] + s_part[1][oo][tid];
    }
    __syncthreads();

    // ---- out = leaky(pre @ Wf^T + bf), 16 warps x 16 d-columns each ----
    const int hb = lane * 8;
    float pr0[8], pr1[8], pr2[8], pr3[8];
#pragma unroll
    for (int j = 0; j < 8; j++) {
        pr0[j] = s_pre[0][hb + j];
        pr1[j] = s_pre[1][hb + j];
        pr2[j] = s_pre[2][hb + j];
        pr3[j] = s_pre[3][hb + j];
    }

    float ov0 = 0.f, ov1 = 0.f, ov2 = 0.f, ov3 = 0.f;
    for (int c = 0; c < 16; c++) {
        const int d = (warp << 4) + c;
        const float4* wf = (const float4*)(Wf + ((size_t)d << 8) + hb);
        float4 f0 = wf[0], f1 = wf[1];
        float fr[8] = {f0.x, f0.y, f0.z, f0.w, f1.x, f1.y, f1.z, f1.w};
        float s0 = 0.f, s1 = 0.f, s2 = 0.f, s3 = 0.f;
#pragma unroll
        for (int j = 0; j < 8; j++) {
            s0 = fmaf(pr0[j], fr[j], s0);
            s1 = fmaf(pr1[j], fr[j], s1);
            s2 = fmaf(pr2[j], fr[j], s2);
            s3 = fmaf(pr3[j], fr[j], s3);
        }
#pragma unroll
        for (int off = 16; off > 0; off >>= 1) {
            s0 += __shfl_xor_sync(0xffffffffu, s0, off);
            s1 += __shfl_xor_sync(0xffffffffu, s1, off);
            s2 += __shfl_xor_sync(0xffffffffu, s2, off);
            s3 += __shfl_xor_sync(0xffffffffu, s3, off);
        }
        if (lane == c) { ov0 = s0; ov1 = s1; ov2 = s2; ov3 = s3; }
    }
    if (lane < 16) {
        const int d = (warp << 4) + lane;
        const float bfd = bf[d];
        float f0v = ov0 + bfd; f0v = (f0v >= 0.f) ? f0v : 0.01f * f0v;
        float f1v = ov1 + bfd; f1v = (f1v >= 0.f) ? f1v : 0.01f * f1v;
        float f2v = ov2 + bfd; f2v = (f2v >= 0.f) ? f2v : 0.01f * f2v;
        float f3v = ov3 + bfd; f3v = (f3v >= 0.f) ? f3v : 0.01f * f3v;
        out[((size_t)(b * O_ + o0 + 0) << 8) + d] = f0v;
        out[((size_t)(b * O_ + o0 + 1) << 8) + d] = f1v;
        out[((size_t)(b * O_ + o0 + 2) << 8) + d] = f2v;
        out[((size_t)(b * O_ + o0 + 3) << 8) + d] = f3v;
    }
}

// ---------------- launch ----------------
extern "C" void kernel_launch(void* const* d_in, const int* in_sizes, int n_in,
                              void* d_out, int out_size)
{
    const float* q  = (const float*)d_in[0];
    const float* k  = (const float*)d_in[1];
    const float* v  = (const float*)d_in[2];
    const int* mask = (const int*)d_in[3];
    const float* W1 = (const float*)d_in[4];
    const float* b1 = (const float*)d_in[5];
    const float* W2 = (const float*)d_in[6];
    // b2 (d_in[7]) cancels in softmax
    const float* Wf = (const float*)d_in[8];
    const float* bf = (const float*)d_in[9];

    float* out  = (float*)d_out;                  // (16,64,256)
    float* attn = out + (size_t)B_ * O_ * D_;     // (16,64,512)

    proj_kernel<<<288, 256>>>(q, k, W1, b1);
    fused_kernel<<<256, 512>>>(v, mask, W2, Wf, bf, out, attn);
}

// round 17
// speedup vs baseline: 1.8458x; 1.3470x over previous
#include <cuda_runtime.h>
#include <cuda_fp16.h>
#include <cstdint>

#define B_ 16
#define O_ 64
#define I_ 512
#define D_ 256
#define OPB 4    // o-values per fused block

// ---------------- scratch (no allocation allowed) ----------------
__device__ float   g_qp[B_ * O_ * D_];          // [b][o][h]  qp' = q@W1q^T + b1
__device__ __half2 g_kpth[B_ * (D_ / 2) * I_];  // [b][hp][i] kp^T as half2 pairs

// ---------------- helpers ----------------
__device__ __forceinline__ uint32_t smem_u32(const void* p) {
    uint32_t a;
    asm("{ .reg .u64 t; cvta.to.shared.u64 t, %1; cvt.u32.u64 %0, t; }"
        : "=r"(a) : "l"(p));
    return a;
}

#define LDSM4(r0, r1, r2, r3, addr)                                           \
    asm volatile("ldmatrix.sync.aligned.m8n8.x4.shared.b16 {%0,%1,%2,%3}, [%4];" \
                 : "=r"(r0), "=r"(r1), "=r"(r2), "=r"(r3) : "r"(addr))

#define MMA16816(d, a0, a1, a2, a3, bb0, bb1)                                 \
    asm volatile("mma.sync.aligned.m16n8k16.row.col.f32.f16.f16.f32 "        \
                 "{%0,%1,%2,%3}, {%4,%5,%6,%7}, {%8,%9}, {%0,%1,%2,%3};"     \
                 : "+f"((d)[0]), "+f"((d)[1]), "+f"((d)[2]), "+f"((d)[3])     \
                 : "r"(a0), "r"(a1), "r"(a2), "r"(a3), "r"(bb0), "r"(bb1))

// ---------------- tensor-core projection (mma.sync, baseline ISA) ----------
// blocks 0..31   : qp  (8 m-tiles x 4 h-tiles), f32 out + b1
// blocks 32..287 : kp  (64 m-tiles x 4 h-tiles), half2-transposed out
// Tile: M=128, N=64, K=256 (smem-resident), 256 threads = 8 warps (4m x 2n),
// each warp m32 x n32; f16 inputs, fp32 accumulate.
#define A_STRIDE 264                       // halves per row (+8 pad)
#define SMEM_B_BYTES_OFF (128 * A_STRIDE * 2)         // 67584
#define SMEM_TOT (SMEM_B_BYTES_OFF + 64 * A_STRIDE * 2 + 128)

__global__ __launch_bounds__(256) void proj_mma(
    const float* __restrict__ q, const float* __restrict__ k,
    const float* __restrict__ W1, const float* __restrict__ b1)
{
    extern __shared__ __align__(16) char smem[];
    __half* As = (__half*)smem;
    __half* Bs = (__half*)(smem + SMEM_B_BYTES_OFF);

    const int bid = blockIdx.x;
    const bool isK = (bid >= 32);
    const int rb = isK ? bid - 32 : bid;
    const int m0 = (rb >> 2) * 128;
    const int h0 = (rb & 3) * 64;
    const float* __restrict__ X = isK ? k : q;
    const int colOff = isK ? 256 : 0;

    const int tid = threadIdx.x;
    const int lane = tid & 31;
    const int wid = tid >> 5;

    // ---- fill A: X[m0..+127][0..255] f32 -> f16, padded row-major ----
#pragma unroll 8
    for (int f = tid; f < 16384; f += 256) {
        const int row = f >> 7;            // 0..127
        const int cp = f & 127;            // half2 index
        float2 xv = *(const float2*)(X + (size_t)(m0 + row) * 256 + cp * 2);
        *(__half2*)(As + row * A_STRIDE + cp * 2) = __floats2half2_rn(xv.x, xv.y);
    }
    // ---- fill B: W1[h0..+63][colOff..+255] -> f16 ----
#pragma unroll 4
    for (int f = tid; f < 8192; f += 256) {
        const int row = f >> 7;            // 0..63
        const int cp = f & 127;
        float2 wv = *(const float2*)(W1 + (size_t)(h0 + row) * 512 + colOff + cp * 2);
        *(__half2*)(Bs + row * A_STRIDE + cp * 2) = __floats2half2_rn(wv.x, wv.y);
    }
    __syncthreads();

    const int wm = (wid >> 1) << 5;        // 0,32,64,96
    const int wn = (wid & 1) << 5;         // 0,32

    float acc[2][4][4];
#pragma unroll
    for (int mt = 0; mt < 2; mt++)
#pragma unroll
        for (int nt = 0; nt < 4; nt++)
#pragma unroll
            for (int r = 0; r < 4; r++) acc[mt][nt][r] = 0.f;

    const uint32_t sA = smem_u32(As);
    const uint32_t sB = smem_u32(Bs);
    // ldmatrix lane addresses (byte offsets advance by 32 per k16 step)
    // A: row = wm + mt*16 + (lane&15), col = (lane>>4)*8
    uint32_t aAddr0 = sA + (uint32_t)((wm + (lane & 15)) * A_STRIDE + ((lane >> 4) << 3)) * 2;
    uint32_t aAddr1 = aAddr0 + 16 * A_STRIDE * 2;
    // B: row = wn + ntp*16 + (lane&7) + ((lane>>4)&1)*8, col = ((lane>>3)&1)*8
    const int brow = (lane & 7) + (((lane >> 4) & 1) << 3);
    const int bcol = ((lane >> 3) & 1) << 3;
    uint32_t bAddr0 = sB + (uint32_t)((wn + brow) * A_STRIDE + bcol) * 2;
    uint32_t bAddr1 = bAddr0 + 16 * A_STRIDE * 2;

#pragma unroll
    for (int ks = 0; ks < 16; ks++) {
        uint32_t a0[4], a1[4], b0[4], b1v[4];
        LDSM4(a0[0], a0[1], a0[2], a0[3], aAddr0 + ks * 32);
        LDSM4(a1[0], a1[1], a1[2], a1[3], aAddr1 + ks * 32);
        LDSM4(b0[0], b0[1], b0[2], b0[3], bAddr0 + ks * 32);
        LDSM4(b1v[0], b1v[1], b1v[2], b1v[3], bAddr1 + ks * 32);

        MMA16816(acc[0][0], a0[0], a0[1], a0[2], a0[3], b0[0], b0[1]);
        MMA16816(acc[0][1], a0[0], a0[1], a0[2], a0[3], b0[2], b0[3]);
        MMA16816(acc[0][2], a0[0], a0[1], a0[2], a0[3], b1v[0], b1v[1]);
        MMA16816(acc[0][3], a0[0], a0[1], a0[2], a0[3], b1v[2], b1v[3]);
        MMA16816(acc[1][0], a1[0], a1[1], a1[2], a1[3], b0[0], b0[1]);
        MMA16816(acc[1][1], a1[0], a1[1], a1[2], a1[3], b0[2], b0[3]);
        MMA16816(acc[1][2], a1[0], a1[1], a1[2], a1[3], b1v[0], b1v[1]);
        MMA16816(acc[1][3], a1[0], a1[1], a1[2], a1[3], b1v[2], b1v[3]);
    }

    // ---- epilogue ----
    // c-frag: c0,c1 -> row (lane>>2), cols (lane&3)*2,+1 ; c2,c3 -> row+8
    if (!isK) {
#pragma unroll
        for (int mt = 0; mt < 2; mt++) {
            const int r0 = m0 + wm + (mt << 4) + (lane >> 2);
#pragma unroll
            for (int nt = 0; nt < 4; nt++) {
                const int h = h0 + wn + (nt << 3) + ((lane & 3) << 1);
                const float bb0 = b1[h], bb1 = b1[h + 1];
                float2 v0 = make_float2(acc[mt][nt][0] + bb0, acc[mt][nt][1] + bb1);
                float2 v1 = make_float2(acc[mt][nt][2] + bb0, acc[mt][nt][3] + bb1);
                *(float2*)(g_qp + (size_t)r0 * 256 + h) = v0;
                *(float2*)(g_qp + (size_t)(r0 + 8) * 256 + h) = v1;
            }
        }
    } else {
        const int b = m0 >> 9;
        const int ib = (m0 & 511) + wm;
#pragma unroll
        for (int mt = 0; mt < 2; mt++) {
            const int i0 = ib + (mt << 4) + (lane >> 2);
#pragma unroll
            for (int nt = 0; nt < 4; nt++) {
                const int hp = ((h0 + wn + (nt << 3)) >> 1) + (lane & 3);
                __half2 v0 = __floats2half2_rn(acc[mt][nt][0], acc[mt][nt][1]);
                __half2 v1 = __floats2half2_rn(acc[mt][nt][2], acc[mt][nt][3]);
                g_kpth[((size_t)(b * 128 + hp) << 9) + i0] = v0;
                g_kpth[((size_t)(b * 128 + hp) << 9) + i0 + 8] = v1;
            }
        }
    }
}

// ---------------- packed f16x2 tanh (MUFU, 2 per op) ----------------
__device__ __forceinline__ __half2 h2tanh_mufu(__half2 x)
{
    unsigned xi = *reinterpret_cast<unsigned*>(&x);
    unsigned yi;
    asm("tanh.approx.f16x2 %0, %1;" : "=r"(yi) : "r"(xi));
    return *reinterpret_cast<__half2*>(&yi);
}

// ---------------- fused score+softmax+attn@v+Wf kernel (R15 best, unchanged) ----
__global__ __launch_bounds__(512) void fused_kernel(
    const float* __restrict__ v, const int* __restrict__ mask,
    const float* __restrict__ W2, const float* __restrict__ Wf,
    const float* __restrict__ bf,
    float* __restrict__ out, float* __restrict__ attn_out)
{
    __shared__ __align__(16) __half2 s_qph[OPB][D_ / 2];
    __shared__ __align__(16) float2 s_w2[D_ / 2];
    __shared__ __align__(16) float s_p[OPB][I_];
    __shared__ __align__(16) float s_part[2][OPB][D_];
    __shared__ __align__(16) float s_pre[OPB][D_];
    __shared__ float s_redA[OPB][16];
    __shared__ float s_redB[OPB][16];

    const int b  = blockIdx.x >> 4;
    const int o0 = (blockIdx.x & 15) << 2;
    const int tid = threadIdx.x;
    const int lane = tid & 31;
    const int warp = tid >> 5;

    {
        const float2* src = (const float2*)(g_qp + ((size_t)(b * O_ + o0) << 8));
        const float2 vv = src[tid];
        s_qph[tid >> 7][tid & 127] = __floats2half2_rn(vv.x, vv.y);
        if (tid < 128) s_w2[tid] = ((const float2*)W2)[tid];
    }
    __syncthreads();

    const __half2* kpt = g_kpth + ((size_t)b << 16) + tid;
    float a0 = 0.f, a1 = 0.f, a2 = 0.f, a3 = 0.f;
#pragma unroll 8
    for (int hp = 0; hp < D_ / 2; hp++) {
        const __half2 kvh = kpt[(size_t)hp << 9];
        const float2 w = s_w2[hp];
        float2 t0 = __half22float2(h2tanh_mufu(__hadd2(s_qph[0][hp], kvh)));
        float2 t1 = __half22float2(h2tanh_mufu(__hadd2(s_qph[1][hp], kvh)));
        float2 t2 = __half22float2(h2tanh_mufu(__hadd2(s_qph[2][hp], kvh)));
        float2 t3 = __half22float2(h2tanh_mufu(__hadd2(s_qph[3][hp], kvh)));
        a0 = fmaf(t0.x, w.x, fmaf(t0.y, w.y, a0));
        a1 = fmaf(t1.x, w.x, fmaf(t1.y, w.y, a1));
        a2 = fmaf(t2.x, w.x, fmaf(t2.y, w.y, a2));
        a3 = fmaf(t3.x, w.x, fmaf(t3.y, w.y, a3));
    }

    const int msk = mask[b * I_ + tid];
    float sc[OPB], e[OPB];
    sc[0] = msk ? -1e30f : a0;
    sc[1] = msk ? -1e30f : a1;
    sc[2] = msk ? -1e30f : a2;
    sc[3] = msk ? -1e30f : a3;
#pragma unroll
    for (int oo = 0; oo < OPB; oo++) {
        float m = sc[oo];
#pragma unroll
        for (int off = 16; off > 0; off >>= 1)
            m = fmaxf(m, __shfl_xor_sync(0xffffffffu, m, off));
        if (lane == 0) s_redA[oo][warp] = m;
    }
    __syncthreads();
#pragma unroll
    for (int oo = 0; oo < OPB; oo++) {
        float mx = s_redA[oo][0];
#pragma unroll
        for (int j = 1; j < 16; j++) mx = fmaxf(mx, s_redA[oo][j]);
        e[oo] = __expf(sc[oo] - mx);
        float ssum = e[oo];
#pragma unroll
        for (int off = 16; off > 0; off >>= 1)
            ssum += __shfl_xor_sync(0xffffffffu, ssum, off);
        if (lane == 0) s_redB[oo][warp] = ssum;
    }
    __syncthreads();
#pragma unroll
    for (int oo = 0; oo < OPB; oo++) {
        float tot = 0.f;
#pragma unroll
        for (int j = 0; j < 16; j++) tot += s_redB[oo][j];
        const float p = e[oo] * __fdividef(1.0f, tot);
        s_p[oo][tid] = p;
        attn_out[((size_t)(b * O_ + o0 + oo) << 9) + tid] = p;
    }
    __syncthreads();

    {
        const int half = tid >> 8;
        const int dd = tid & 255;
        const float* vb = v + ((size_t)b << 17) + ((size_t)half << 16) + dd;
        float ac0 = 0.f, ac1 = 0.f, ac2 = 0.f, ac3 = 0.f;
#pragma unroll 2
        for (int ii = 0; ii < 256; ii += 4) {
            const int i = (half << 8) + ii;
            float4 p0 = *(const float4*)&s_p[0][i];
            float4 p1 = *(const float4*)&s_p[1][i];
            float4 p2 = *(const float4*)&s_p[2][i];
            float4 p3 = *(const float4*)&s_p[3][i];
            float v0 = vb[(ii + 0) << 8];
            float v1 = vb[(ii + 1) << 8];
            float v2 = vb[(ii + 2) << 8];
            float v3 = vb[(ii + 3) << 8];
            ac0 = fmaf(p0.x, v0, ac0); ac1 = fmaf(p1.x, v0, ac1);
            ac2 = fmaf(p2.x, v0, ac2); ac3 = fmaf(p3.x, v0, ac3);
            ac0 = fmaf(p0.y, v1, ac0); ac1 = fmaf(p1.y, v1, ac1);
            ac2 = fmaf(p2.y, v1, ac2); ac3 = fmaf(p3.y, v1, ac3);
            ac0 = fmaf(p0.z, v2, ac0); ac1 = fmaf(p1.z, v2, ac1);
            ac2 = fmaf(p2.z, v2, ac2); ac3 = fmaf(p3.z, v2, ac3);
            ac0 = fmaf(p0.w, v3, ac0); ac1 = fmaf(p1.w, v3, ac1);
            ac2 = fmaf(p2.w, v3, ac2); ac3 = fmaf(p3.w, v3, ac3);
        }
        s_part[half][0][dd] = ac0;
        s_part[half][1][dd] = ac1;
        s_part[half][2][dd] = ac2;
        s_part[half][3][dd] = ac3;
    }
    __syncthreads();
    if (tid < 256) {
#pragma unroll
        for (int oo = 0; oo < OPB; oo++)
            s_pre[oo][tid] = s_part[0][oo][tid] + s_part[1][oo][tid];
    }
    __syncthreads();

    const int hb = lane * 8;
    float pr0[8], pr1[8], pr2[8], pr3[8];
#pragma unroll
    for (int j = 0; j < 8; j++) {
        pr0[j] = s_pre[0][hb + j];
        pr1[j] = s_pre[1][hb + j];
        pr2[j] = s_pre[2][hb + j];
        pr3[j] = s_pre[3][hb + j];
    }

    float ov0 = 0.f, ov1 = 0.f, ov2 = 0.f, ov3 = 0.f;
    for (int c = 0; c < 16; c++) {
        const int dd = (warp << 4) + c;
        const float4* wf = (const float4*)(Wf + ((size_t)dd << 8) + hb);
        float4 f0 = wf[0], f1 = wf[1];
        float fr[8] = {f0.x, f0.y, f0.z, f0.w, f1.x, f1.y, f1.z, f1.w};
        float s0 = 0.f, s1 = 0.f, s2 = 0.f, s3 = 0.f;
#pragma unroll
        for (int j = 0; j < 8; j++) {
            s0 = fmaf(pr0[j], fr[j], s0);
            s1 = fmaf(pr1[j], fr[j], s1);
            s2 = fmaf(pr2[j], fr[j], s2);
            s3 = fmaf(pr3[j], fr[j], s3);
        }
#pragma unroll
        for (int off = 16; off > 0; off >>= 1) {
            s0 += __shfl_xor_sync(0xffffffffu, s0, off);
            s1 += __shfl_xor_sync(0xffffffffu, s1, off);
            s2 += __shfl_xor_sync(0xffffffffu, s2, off);
            s3 += __shfl_xor_sync(0xffffffffu, s3, off);
        }
        if (lane == c) { ov0 = s0; ov1 = s1; ov2 = s2; ov3 = s3; }
    }
    if (lane < 16) {
        const int dd = (warp << 4) + lane;
        const float bfd = bf[dd];
        float f0v = ov0 + bfd; f0v = (f0v >= 0.f) ? f0v : 0.01f * f0v;
        float f1v = ov1 + bfd; f1v = (f1v >= 0.f) ? f1v : 0.01f * f1v;
        float f2v = ov2 + bfd; f2v = (f2v >= 0.f) ? f2v : 0.01f * f2v;
        float f3v = ov3 + bfd; f3v = (f3v >= 0.f) ? f3v : 0.01f * f3v;
        out[((size_t)(b * O_ + o0 + 0) << 8) + dd] = f0v;
        out[((size_t)(b * O_ + o0 + 1) << 8) + dd] = f1v;
        out[((size_t)(b * O_ + o0 + 2) << 8) + dd] = f2v;
        out[((size_t)(b * O_ + o0 + 3) << 8) + dd] = f3v;
    }
}

// ---------------- launch ----------------
extern "C" void kernel_launch(void* const* d_in, const int* in_sizes, int n_in,
                              void* d_out, int out_size)
{
    const float* q  = (const float*)d_in[0];
    const float* k  = (const float*)d_in[1];
    const float* v  = (const float*)d_in[2];
    const int* mask = (const int*)d_in[3];
    const float* W1 = (const float*)d_in[4];
    const float* b1 = (const float*)d_in[5];
    const float* W2 = (const float*)d_in[6];
    // b2 (d_in[7]) cancels in softmax
    const float* Wf = (const float*)d_in[8];
    const float* bf = (const float*)d_in[9];

    float* out  = (float*)d_out;                  // (16,64,256)
    float* attn = out + (size_t)B_ * O_ * D_;     // (16,64,512)

    static int smem_set = 0;
    if (!smem_set) {
        cudaFuncSetAttribute(proj_mma, cudaFuncAttributeMaxDynamicSharedMemorySize, SMEM_TOT);
        smem_set = 1;
    }
    proj_mma<<<288, 256, SMEM_TOT>>>(q, k, W1, b1);
    fused_kernel<<<256, 512>>>(v, mask, W2, Wf, bf, out, attn);
}